// round 12
// baseline (speedup 1.0000x reference)
#include <cuda_runtime.h>
#include <math.h>

// ------------------------------ scratch (device globals; allocation-free) ---
__device__ float g_conv1[2 * 64 * 512 * 512];   // 128 MB (style, content)
__device__ float g_conv2[2 * 32 * 256 * 256];   // 16 MB
__device__ float g_ff[2 * 16 * 128 * 128];      // conv3 outputs (style, content)
__device__ float g_X[64 * 65536];               // compressed features (uncentered)
__device__ float g_trans[64 * 65536];           // transformed features
__device__ unsigned short g_packed_c[65536];
__device__ unsigned short g_packed_s[65536];
__device__ int g_partial[256][36];              // per-block mask counts
__device__ int g_cnt_s256[9];
__device__ int g_active[9];
__device__ int g_gidx[2 * 9 * 16384];
__device__ int g_gN[2 * 9];
__device__ float g_pooled[2 * 9 * 4096];
__device__ float g_mats[2 * 9 * 4096];      // [0..8]=style sM, [9..17]=content cM
__device__ float g_T[9 * 4096];
__device__ float g_rowsum[64];
__device__ float g_xmean[64];
__device__ float g_ssum[9 * 256];
__device__ float g_smean[9 * 256];
__device__ int g_reg[65536];

// ------------------------------ packed f32x2 helpers ------------------------
__device__ __forceinline__ unsigned long long pk2(float lo, float hi) {
    unsigned long long r;
    asm("mov.b64 %0, {%1, %2};" : "=l"(r) : "f"(lo), "f"(hi));
    return r;
}
__device__ __forceinline__ unsigned long long fma2(unsigned long long a,
                                                   unsigned long long b,
                                                   unsigned long long c) {
    unsigned long long d;
    asm("fma.rn.f32x2 %0, %1, %2, %3;" : "=l"(d) : "l"(a), "l"(b), "l"(c));
    return d;
}
__device__ __forceinline__ void upk2(unsigned long long v, float& lo, float& hi) {
    asm("mov.b64 {%0, %1}, %2;" : "=f"(lo), "=f"(hi) : "l"(v));
}

// ------------------------------------------------------ conv body (shared) ---
// 3x3, stride 2, pad 1.  16 x TH output tile.  Intra-warp oc split:
//   px2 = tid&7, ocg = (tid>>3)%OCG, pyt = tid/(8*OCG)
template <int IC, int OC, int ICB, int OCT, int TH, bool RELU>
__device__ __forceinline__ void conv_body(
    char* smbase, int bx, int by,
    const float* __restrict__ in, const float* __restrict__ w,
    const float* __restrict__ bias, float* __restrict__ out,
    int inH, int inW) {
    constexpr int OCG = OC / OCT;
    constexpr int PAIRS = 8 * TH;
    constexpr int PYT = 32 / OCG;          // py-thread slots (256/(8*OCG))
    constexpr int PH = PAIRS / (8 * PYT);  // pair-rows per thread
    constexpr int ROWS = 2 * TH + 1;
    static_assert(PH >= 1, "tile too small");

    float* s_in = reinterpret_cast<float*>(smbase);                 // [ICB][ROWS][36]
    unsigned long long* s_w2 = reinterpret_cast<unsigned long long*>(
        smbase + ICB * ROWS * 36 * 4);                              // [ICB][9][OC]

    const int tid = threadIdx.x;
    const int px2 = tid & 7;
    const int ocg = (tid >> 3) % OCG;
    const int pyt = tid / (8 * OCG);
    const int px = px2 * 2;
    const int py = pyt * PH;
    const int outH = inH >> 1, outW = inW >> 1;
    const int ox0 = bx * 16, oy0 = by * TH;

    unsigned long long acc[OCT][PH];
    #pragma unroll
    for (int o = 0; o < OCT; o++) {
        float b = bias[ocg * OCT + o];
        #pragma unroll
        for (int ph = 0; ph < PH; ph++) acc[o][ph] = pk2(b, b);
    }

    for (int c0 = 0; c0 < IC; c0 += ICB) {
        __syncthreads();
        for (int idx = tid; idx < ICB * ROWS * 33; idx += 256) {
            int c = idx / (ROWS * 33), r = idx % (ROWS * 33), yy = r / 33, xx = r % 33;
            int iy = 2 * oy0 - 1 + yy, ix = 2 * ox0 - 1 + xx;
            float v = 0.f;
            if (iy >= 0 && iy < inH && ix >= 0 && ix < inW)
                v = in[((size_t)(c0 + c) * inH + iy) * inW + ix];
            s_in[(c * ROWS + yy) * 36 + xx] = v;
        }
        for (int idx = tid; idx < ICB * 9 * OC; idx += 256) {
            int c = idx / (9 * OC), r = idx % (9 * OC), k = r / OC, o = r % OC;
            float wv = w[(o * IC + c0 + c) * 9 + k];
            s_w2[idx] = pk2(wv, wv);
        }
        __syncthreads();
        #pragma unroll
        for (int c = 0; c < ICB; c++)
            #pragma unroll
            for (int ky = 0; ky < 3; ky++) {
                // hoisted row loads: 6 floats per ph via LDS.128 + LDS.64
                float4 v03[PH];
                float2 v45[PH];
                #pragma unroll
                for (int ph = 0; ph < PH; ph++) {
                    const float* rp = &s_in[(c * ROWS + 2 * (py + ph) + ky) * 36 + 2 * px];
                    v03[ph] = *reinterpret_cast<const float4*>(rp);
                    v45[ph] = *reinterpret_cast<const float2*>(rp + 4);
                }
                #pragma unroll
                for (int kx = 0; kx < 3; kx++) {
                    unsigned long long iv[PH];
                    #pragma unroll
                    for (int ph = 0; ph < PH; ph++)
                        iv[ph] = (kx == 0) ? pk2(v03[ph].x, v03[ph].z)
                               : (kx == 1) ? pk2(v03[ph].y, v03[ph].w)
                                           : pk2(v03[ph].z, v45[ph].x);
                    const ulonglong2* wp = reinterpret_cast<const ulonglong2*>(
                        &s_w2[(c * 9 + ky * 3 + kx) * OC + ocg * OCT]);
                    #pragma unroll
                    for (int q = 0; q < OCT / 2; q++) {
                        ulonglong2 wv = wp[q];
                        #pragma unroll
                        for (int ph = 0; ph < PH; ph++) {
                            acc[2 * q][ph] = fma2(wv.x, iv[ph], acc[2 * q][ph]);
                            acc[2 * q + 1][ph] = fma2(wv.y, iv[ph], acc[2 * q + 1][ph]);
                        }
                    }
                }
            }
    }
    #pragma unroll
    for (int o = 0; o < OCT; o++) {
        int oc = ocg * OCT + o;
        #pragma unroll
        for (int ph = 0; ph < PH; ph++) {
            float lo, hi;
            upk2(acc[o][ph], lo, hi);
            if (RELU) { lo = fmaxf(lo, 0.f); hi = fmaxf(hi, 0.f); }
            int oy = oy0 + py + ph, ox = ox0 + px;
            float2* op = reinterpret_cast<float2*>(&out[((size_t)oc * outH + oy) * outW + ox]);
            *op = make_float2(lo, hi);
        }
    }
}

// ------------------------------------------------- init body (16 blocks) ---
__device__ void init_body(int blk, const float* __restrict__ sfcb,
                          const float* __restrict__ cfcb) {
    int t = blk * 256 + threadIdx.x;              // 0..4095
    float sv = sfcb[t], cv = cfcb[t];
    #pragma unroll
    for (int i = 0; i < 9; i++) {
        g_mats[i * 4096 + t] = sv;
        g_mats[(9 + i) * 4096 + t] = cv;
        g_pooled[i * 4096 + t] = 0.f;
        g_pooled[(9 + i) * 4096 + t] = 0.f;
    }
    if (t < 64) g_rowsum[t] = 0.f;
    if (t < 2304) g_ssum[t] = 0.f;
}

// --------------------- masks body (256 blocks; per-block partial counts) ---
__device__ void masks_body(int blk, const int* __restrict__ cm,
                           const int* __restrict__ smk, int* s_cnt) {
    int tid = threadIdx.x;
    if (tid < 36) s_cnt[tid] = 0;
    __syncthreads();
    int p = blk * 256 + tid;
    int y = p >> 8, x = p & 255;
    int even = ((y & 1) == 0) && ((x & 1) == 0);
    unsigned pc = 0, ps = 0;
    #pragma unroll
    for (int i = 0; i < 9; i++) {
        int cb = (cm[i * 65536 + p] == 1);
        int sb = (smk[i * 65536 + p] == 1);
        if (cb) pc |= 1u << i;
        if (sb) ps |= 1u << i;
        unsigned bc = __ballot_sync(0xffffffffu, cb);
        unsigned bs = __ballot_sync(0xffffffffu, sb);
        unsigned bc1 = __ballot_sync(0xffffffffu, cb && even);
        unsigned bs1 = __ballot_sync(0xffffffffu, sb && even);
        if ((tid & 31) == 0) {
            atomicAdd(&s_cnt[i], __popc(bc));
            atomicAdd(&s_cnt[9 + i], __popc(bs));
            atomicAdd(&s_cnt[18 + i], __popc(bc1));
            atomicAdd(&s_cnt[27 + i], __popc(bs1));
        }
    }
    g_packed_c[p] = (unsigned short)pc;
    g_packed_s[p] = (unsigned short)ps;
    __syncthreads();
    if (tid < 36) g_partial[blk][tid] = s_cnt[tid];
}

// -------- compress half: X[o-half] = compress_w @ cF + b, 32 oc per block ---
__device__ void compress_half(char* smbase, int blk, const float* __restrict__ cF,
                              const float* __restrict__ cw, const float* __restrict__ cb) {
    unsigned long long* s_w = reinterpret_cast<unsigned long long*>(smbase); // [64][16]
    int tid = threadIdx.x;
    int p = (blk >> 1) * 256 + tid;
    int o2base = (blk & 1) * 16;
    unsigned long long acc[16];
    #pragma unroll
    for (int o2 = 0; o2 < 16; o2++) {
        int og = o2base + o2;
        acc[o2] = pk2(cb[2 * og], cb[2 * og + 1]);
    }
    for (int c0 = 0; c0 < 256; c0 += 64) {
        __syncthreads();
        for (int idx = tid; idx < 1024; idx += 256) {
            int c = idx >> 4, o2 = idx & 15;
            int og = o2base + o2;
            s_w[idx] = pk2(cw[(2 * og) * 256 + c0 + c],
                           cw[(2 * og + 1) * 256 + c0 + c]);
        }
        __syncthreads();
        for (int c = 0; c < 64; c++) {
            float v = cF[(c0 + c) * 65536 + p];
            unsigned long long vp = pk2(v, v);
            const ulonglong2* wq = reinterpret_cast<const ulonglong2*>(&s_w[c * 16]);
            #pragma unroll
            for (int q = 0; q < 8; q++) {
                ulonglong2 wv = wq[q];
                acc[2 * q] = fma2(wv.x, vp, acc[2 * q]);
                acc[2 * q + 1] = fma2(wv.y, vp, acc[2 * q + 1]);
            }
        }
    }
    int lane = tid & 31;
    #pragma unroll
    for (int o2 = 0; o2 < 16; o2++) {
        int og = o2base + o2;
        float lo, hi;
        upk2(acc[o2], lo, hi);
        g_X[(2 * og) * 65536 + p] = lo;
        g_X[(2 * og + 1) * 65536 + p] = hi;
        float a = lo, b = hi;
        a += __shfl_down_sync(0xffffffffu, a, 16);
        b += __shfl_down_sync(0xffffffffu, b, 16);
        a += __shfl_down_sync(0xffffffffu, a, 8);
        b += __shfl_down_sync(0xffffffffu, b, 8);
        a += __shfl_down_sync(0xffffffffu, a, 4);
        b += __shfl_down_sync(0xffffffffu, b, 4);
        a += __shfl_down_sync(0xffffffffu, a, 2);
        b += __shfl_down_sync(0xffffffffu, b, 2);
        a += __shfl_down_sync(0xffffffffu, a, 1);
        b += __shfl_down_sync(0xffffffffu, b, 1);
        if (lane == 0) {
            atomicAdd(&g_rowsum[2 * og], a);
            atomicAdd(&g_rowsum[2 * og + 1], b);
        }
    }
}

// --------------------- per-region style channel sums (512 blocks, 2/chan) ---
__device__ void stylesum_body(int blk, const float* __restrict__ sF) {
    int tid = threadIdx.x;
    int c = blk >> 1;
    int base = (blk & 1) * 32768;
    float acc[9];
    #pragma unroll
    for (int i = 0; i < 9; i++) acc[i] = 0.f;
    const float* fc = sF + c * 65536;
    for (int k = 0; k < 128; k++) {
        int p = base + k * 256 + tid;
        float v = fc[p];
        unsigned bits = g_packed_s[p];
        #pragma unroll
        for (int i = 0; i < 9; i++)
            acc[i] += ((bits >> i) & 1) ? v : 0.f;
    }
    int lane = tid & 31;
    #pragma unroll
    for (int i = 0; i < 9; i++) {
        float v = acc[i];
        v += __shfl_down_sync(0xffffffffu, v, 16);
        v += __shfl_down_sync(0xffffffffu, v, 8);
        v += __shfl_down_sync(0xffffffffu, v, 4);
        v += __shfl_down_sync(0xffffffffu, v, 2);
        v += __shfl_down_sync(0xffffffffu, v, 1);
        if (lane == 0) atomicAdd(&g_ssum[i * 256 + c], v);
    }
}

// ------------- FAT 1: conv1 (4096 blocks) + masks (256) + init (16) ---------
__global__ __launch_bounds__(256, 4)
void k_fat1(const float* __restrict__ style, const float* __restrict__ content,
            const float* __restrict__ w1s, const float* __restrict__ w1c,
            const float* __restrict__ b1s, const float* __restrict__ b1c,
            const int* __restrict__ cm, const int* __restrict__ smk,
            const float* __restrict__ sfcb, const float* __restrict__ cfcb) {
    __shared__ __align__(16) char sm[3 * 17 * 36 * 4 + 3 * 9 * 64 * 8];  // 21168
    int b = blockIdx.x;
    if (b < 16) {
        init_body(b, sfcb, cfcb);
    } else if (b < 272) {
        masks_body(b - 16, cm, smk, reinterpret_cast<int*>(sm));
    } else {
        int bb = b - 272;
        int bx = bb & 31, by = (bb >> 5) & 63, img = bb >> 11;
        conv_body<3, 64, 3, 8, 8, true>(
            sm, bx, by, img ? content : style, img ? w1c : w1s,
            img ? b1c : b1s, &g_conv1[(size_t)img * 64 * 512 * 512], 1024, 1024);
    }
}

// ---- FAT 2: conv2 + compress + stylesum (512 each, striped by b % 3) -------
__global__ __launch_bounds__(256, 4)
void k_fat2(const float* __restrict__ w2s, const float* __restrict__ w2c,
            const float* __restrict__ b2s, const float* __restrict__ b2c,
            const float* __restrict__ cF, const float* __restrict__ cw,
            const float* __restrict__ cb, const float* __restrict__ sF) {
    __shared__ __align__(16) char sm[4 * 33 * 36 * 4 + 4 * 9 * 32 * 8];  // 28224
    int b = blockIdx.x;
    int role = b % 3, idx = b / 3;
    if (role == 0) {
        int bx = idx & 15, by = (idx >> 4) & 15, img = idx >> 8;
        conv_body<64, 32, 4, 8, 16, true>(
            sm, bx, by, &g_conv1[(size_t)img * 64 * 512 * 512],
            img ? w2c : w2s, img ? b2c : b2s,
            &g_conv2[(size_t)img * 32 * 256 * 256], 512, 512);
    } else if (role == 1) {
        compress_half(sm, idx, cF, cw, cb);
    } else {
        stylesum_body(idx, sF);
    }
}

// ---------------------------------------------------------------- conv3 ---
__global__ __launch_bounds__(256, 2)
void k_conv3(const float* __restrict__ w3s, const float* __restrict__ w3c,
             const float* __restrict__ b3s, const float* __restrict__ b3c) {
    __shared__ __align__(16) char sm[4 * 33 * 36 * 4 + 4 * 9 * 16 * 8];  // 23616
    int img = blockIdx.z;
    conv_body<32, 16, 4, 8, 16, false>(
        sm, blockIdx.x, blockIdx.y, &g_conv2[(size_t)img * 32 * 256 * 256],
        img ? w3c : w3s, img ? b3c : b3s,
        &g_ff[(size_t)img * 16 * 128 * 128], 256, 256);
}

// ----------------- active flags + s256 counts (single block, 256 threads) ---
__global__ void k_active() {
    int tid = threadIdx.x;
    __shared__ int sums[36];
    if (tid < 36) {
        int s = 0;
        for (int b = 0; b < 256; b++) s += g_partial[b][tid];
        sums[tid] = s;
    }
    __syncthreads();
    if (tid < 9) {
        g_active[tid] = (sums[tid] >= 10) && (sums[9 + tid] >= 10) &&
                        (sums[18 + tid] >= 10) && (sums[27 + tid] >= 10);
        g_cnt_s256[tid] = sums[9 + tid];
    }
}

// ----------------------------- per-(image,region) mask compaction (128^2) ---
__global__ void k_gather() {
    int img = blockIdx.x / 9, i = blockIdx.x % 9;
    int tid = threadIdx.x, lane = tid & 31, wid = tid >> 5;
    const unsigned short* pk = (img == 0) ? g_packed_s : g_packed_c;

    __shared__ unsigned s_words[512];
    __shared__ int s_wsum[8];

    for (int widx = wid; widx < 512; widx += 8) {
        int pos = widx * 32 + lane;
        int yy = pos >> 7, xx = pos & 127;
        int p = (yy << 9) | (xx << 1);          // (2y)*256 + 2x
        unsigned b = __ballot_sync(0xffffffffu, (pk[p] >> i) & 1);
        if (lane == 0) s_words[widx] = b;
    }
    __syncthreads();

    unsigned w0 = s_words[2 * tid], w1 = s_words[2 * tid + 1];
    int c2 = __popc(w0) + __popc(w1);
    int v = c2;
    #pragma unroll
    for (int d = 1; d < 32; d <<= 1) {
        int n = __shfl_up_sync(0xffffffffu, v, d);
        if (lane >= d) v += n;
    }
    if (lane == 31) s_wsum[wid] = v;
    __syncthreads();
    if (wid == 0 && lane < 8) {
        int t = s_wsum[lane];
        #pragma unroll
        for (int d = 1; d < 8; d <<= 1) {
            int n = __shfl_up_sync(0xffu, t, d);
            if (lane >= d) t += n;
        }
        s_wsum[lane] = t;
    }
    __syncthreads();
    int base = v - c2 + (wid ? s_wsum[wid - 1] : 0);   // exclusive prefix

    int* gx = g_gidx + (img * 9 + i) * 16384;
    int o = base, pb = tid * 64;
    unsigned m = w0;
    while (m) { int b = __ffs(m) - 1; m &= m - 1; gx[o++] = pb + b; }
    m = w1; pb += 32;
    while (m) { int b = __ffs(m) - 1; m &= m - 1; gx[o++] = pb + b; }
    if (tid == 255) g_gN[img * 9 + i] = base + c2;
}

// ------------------------- adaptive max pool 256: block per (img,reg,chan) ---
__global__ void k_pool() {
    int img = blockIdx.x / 9, i = blockIdx.x % 9, c = blockIdx.y;
    int N = g_gN[img * 9 + i];
    if (N < 10) return;
    int j = threadIdx.x;                       // bin 0..255
    int s = (j * N) >> 8;
    int e = ((j + 1) * N + 255) >> 8;
    const float* fc = g_ff + img * 16 * 16384 + c * 16384;
    const int* gx = g_gidx + (img * 9 + i) * 16384;
    float m = -3.4e38f;
    for (int r = s; r < e; r++) m = fmaxf(m, fc[gx[r]]);
    g_pooled[(img * 9 + i) * 4096 + c * 256 + j] = m;
}

// ------ FC: mats[img][i][r] += fcw[r,:] @ pooled[img][i]  (coalesced k) -----
__global__ __launch_bounds__(256, 2)
void k_fc(const float* __restrict__ sfcw, const float* __restrict__ cfcw) {
    int img = blockIdx.y;
    const float* fcw = (img == 0) ? sfcw : cfcw;
    __shared__ float sp[9][1024];
    int tid = threadIdx.x, lane = tid & 31, wid = tid >> 5;
    int r0 = blockIdx.x * 32 + wid * 4;
    float acc[4][9];
    #pragma unroll
    for (int rr = 0; rr < 4; rr++)
        #pragma unroll
        for (int i = 0; i < 9; i++) acc[rr][i] = 0.f;

    for (int kc = 0; kc < 4096; kc += 1024) {
        __syncthreads();
        for (int idx = tid * 4; idx < 9216; idx += 1024) {
            int i = idx >> 10, kk = idx & 1023;
            *(float4*)&sp[i][kk] =
                *(const float4*)&g_pooled[(img * 9 + i) * 4096 + kc + kk];
        }
        __syncthreads();
        for (int kk = lane * 4; kk < 1024; kk += 128) {
            float4 p4[9];
            #pragma unroll
            for (int i = 0; i < 9; i++) p4[i] = *(const float4*)&sp[i][kk];
            #pragma unroll
            for (int rr = 0; rr < 4; rr++) {
                float4 w4 = *(const float4*)&fcw[(size_t)(r0 + rr) * 4096 + kc + kk];
                #pragma unroll
                for (int i = 0; i < 9; i++)
                    acc[rr][i] += w4.x * p4[i].x + w4.y * p4[i].y +
                                  w4.z * p4[i].z + w4.w * p4[i].w;
            }
        }
    }
    #pragma unroll
    for (int rr = 0; rr < 4; rr++)
        #pragma unroll
        for (int i = 0; i < 9; i++) {
            float v = acc[rr][i];
            #pragma unroll
            for (int off = 16; off; off >>= 1)
                v += __shfl_xor_sync(0xffffffffu, v, off);
            if (lane == 0) g_mats[(img * 9 + i) * 4096 + r0 + rr] += v;
        }
}

// ----------------------------------------------------- T_i = sM_i @ cM_i ---
__global__ void k_T() {
    int i = blockIdx.x;
    if (!g_active[i]) return;
    __shared__ float sA[4096], sB[4096];
    for (int idx = threadIdx.x; idx < 4096; idx += 256) {
        sA[idx] = g_mats[i * 4096 + idx];          // sM
        sB[idx] = g_mats[(9 + i) * 4096 + idx];    // cM
    }
    __syncthreads();
    for (int idx = threadIdx.x; idx < 4096; idx += 256) {
        int o = idx >> 6, n = idx & 63;
        float a = 0.f;
        #pragma unroll 16
        for (int k = 0; k < 64; k++) a += sA[o * 64 + k] * sB[k * 64 + n];
        g_T[i * 4096 + idx] = a;
    }
}

__global__ void k_finalize() {
    int t = blockIdx.x * 256 + threadIdx.x;
    if (t < 64) g_xmean[t] = g_rowsum[t] * (1.f / 65536.f);
    if (t < 2304) {
        int i = t >> 8;
        int n = g_cnt_s256[i];
        g_smean[t] = (n > 0) ? g_ssum[t] / (float)n : 0.f;
    }
}

// --------------- trans = (region ? T_reg @ Xc : Xc), last active region wins ---
__global__ void k_trans() {
    extern __shared__ float sT[];              // 9 * 4100 floats
    __shared__ float sxm[64];
    __shared__ int sact[9];
    int tid = threadIdx.x;
    for (int idx = tid; idx < 9 * 4096; idx += 256)
        sT[(idx >> 12) * 4100 + (idx & 4095)] = g_T[idx];
    if (tid < 64) sxm[tid] = g_xmean[tid];
    if (tid < 9) sact[tid] = g_active[tid];
    __syncthreads();
    int p = blockIdx.x * 256 + tid;
    unsigned bits = g_packed_c[p];
    int reg = -1;
    #pragma unroll
    for (int i = 8; i >= 0; i--)
        if (reg < 0 && sact[i] && ((bits >> i) & 1)) reg = i;
    float x[64];
    #pragma unroll
    for (int o = 0; o < 64; o++) x[o] = g_X[o * 65536 + p] - sxm[o];
    if (reg >= 0) {
        const float* T = &sT[reg * 4100];
        for (int o = 0; o < 64; o++) {
            const float4* t4 = reinterpret_cast<const float4*>(&T[o * 64]);
            float a0 = 0.f, a1 = 0.f, a2 = 0.f, a3 = 0.f;
            #pragma unroll
            for (int q = 0; q < 16; q++) {
                float4 tv = t4[q];
                a0 = fmaf(tv.x, x[4 * q], a0);
                a1 = fmaf(tv.y, x[4 * q + 1], a1);
                a2 = fmaf(tv.z, x[4 * q + 2], a2);
                a3 = fmaf(tv.w, x[4 * q + 3], a3);
            }
            g_trans[o * 65536 + p] = (a0 + a1) + (a2 + a3);
        }
    } else {
        #pragma unroll
        for (int o = 0; o < 64; o++) g_trans[o * 65536 + p] = x[o];
    }
    g_reg[p] = reg;
}

// ------- out = unzip_w @ trans + unzip_b + smean[region]  (f32x2 oc pairs) ---
__global__ __launch_bounds__(256, 2)
void k_unzip(const float* __restrict__ uw, const float* __restrict__ ub,
             float* __restrict__ out) {
    extern __shared__ unsigned long long dynsm[];
    unsigned long long* s_w2 = dynsm;              // [c][o2] = 64*128 u64
    unsigned long long* s_b2 = dynsm + 8192;       // [128]
    float* s_m = (float*)(dynsm + 8192 + 128);     // [9*256]
    int tid = threadIdx.x;
    for (int idx = tid; idx < 8192; idx += 256) {
        int c = idx >> 7, o2 = idx & 127;
        s_w2[idx] = pk2(uw[(2 * o2) * 64 + c], uw[(2 * o2 + 1) * 64 + c]);
    }
    if (tid < 128) s_b2[tid] = pk2(ub[2 * tid], ub[2 * tid + 1]);
    for (int idx = tid; idx < 2304; idx += 256) s_m[idx] = g_smean[idx];
    __syncthreads();
    int p = blockIdx.x * 256 + tid;
    float tr[64];
    #pragma unroll
    for (int c = 0; c < 64; c++) tr[c] = g_trans[c * 65536 + p];
    int reg = g_reg[p];
    #pragma unroll 1
    for (int t = 0; t < 8; t++) {                  // 8 tiles of 16 oc-pairs
        unsigned long long acc[16];
        #pragma unroll
        for (int q = 0; q < 16; q++) acc[q] = s_b2[t * 16 + q];
        #pragma unroll 8
        for (int c = 0; c < 64; c++) {
            unsigned long long xd = pk2(tr[c], tr[c]);
            const ulonglong2* wp =
                reinterpret_cast<const ulonglong2*>(&s_w2[c * 128 + t * 16]);
            #pragma unroll
            for (int q2 = 0; q2 < 8; q2++) {
                ulonglong2 wv = wp[q2];
                acc[2 * q2] = fma2(wv.x, xd, acc[2 * q2]);
                acc[2 * q2 + 1] = fma2(wv.y, xd, acc[2 * q2 + 1]);
            }
        }
        #pragma unroll
        for (int q = 0; q < 16; q++) {
            float lo, hi;
            upk2(acc[q], lo, hi);
            int o = (t * 16 + q) * 2;
            if (reg >= 0) { lo += s_m[reg * 256 + o]; hi += s_m[reg * 256 + o + 1]; }
            out[(size_t)o * 65536 + p] = lo;
            out[(size_t)(o + 1) * 65536 + p] = hi;
        }
    }
}

// ---------------------------------------------------------------- launch ---
extern "C" void kernel_launch(void* const* d_in, const int* in_sizes, int n_in,
                              void* d_out, int out_size) {
    (void)in_sizes; (void)n_in; (void)out_size;
    const float* cF         = (const float*)d_in[0];
    const float* sF         = (const float*)d_in[1];
    const float* content    = (const float*)d_in[2];
    const float* style      = (const float*)d_in[3];
    const int*   cmasks     = (const int*)d_in[4];
    const int*   smasks     = (const int*)d_in[5];
    const float* compress_w = (const float*)d_in[6];
    const float* compress_b = (const float*)d_in[7];
    const float* unzip_w    = (const float*)d_in[8];
    const float* unzip_b    = (const float*)d_in[9];
    const float* s_w1 = (const float*)d_in[10]; const float* s_b1 = (const float*)d_in[11];
    const float* s_w2 = (const float*)d_in[12]; const float* s_b2 = (const float*)d_in[13];
    const float* s_w3 = (const float*)d_in[14]; const float* s_b3 = (const float*)d_in[15];
    const float* s_fcw = (const float*)d_in[16]; const float* s_fcb = (const float*)d_in[17];
    const float* c_w1 = (const float*)d_in[18]; const float* c_b1 = (const float*)d_in[19];
    const float* c_w2 = (const float*)d_in[20]; const float* c_b2 = (const float*)d_in[21];
    const float* c_w3 = (const float*)d_in[22]; const float* c_b3 = (const float*)d_in[23];
    const float* c_fcw = (const float*)d_in[24]; const float* c_fcb = (const float*)d_in[25];
    float* out = (float*)d_out;

    // opt-in dynamic smem (idempotent; host API, capture-safe)
    cudaFuncSetAttribute(k_trans, cudaFuncAttributeMaxDynamicSharedMemorySize, 9 * 4100 * 4);
    cudaFuncSetAttribute(k_unzip, cudaFuncAttributeMaxDynamicSharedMemorySize,
                         8192 * 8 + 128 * 8 + 2304 * 4);

    // 1: conv1 + masks + init (independent roles fused, small roles first)
    k_fat1<<<4368, 256>>>(style, content, s_w1, c_w1, s_b1, c_b1,
                          cmasks, smasks, s_fcb, c_fcb);
    // 2: active flags + counts (needs masks partials)
    k_active<<<1, 256>>>();
    // 3: mask compaction (needs packed masks)
    k_gather<<<18, 256>>>();
    // 4 <- profiled: conv2 + compress + stylesum, striped for pipe mixing
    k_fat2<<<1536, 256>>>(s_w2, c_w2, s_b2, c_b2, cF, compress_w, compress_b, sF);
    // 5: conv3
    k_conv3<<<dim3(8, 8, 2), 256>>>(s_w3, c_w3, s_b3, c_b3);
    // 6-9: pool, fc, T, finalize
    k_pool<<<dim3(18, 16), 256>>>();
    k_fc<<<dim3(128, 2), 256>>>(s_fcw, c_fcw);
    k_T<<<9, 256>>>();
    k_finalize<<<9, 256>>>();
    // 10-11: trans, unzip
    k_trans<<<256, 256, 9 * 4100 * 4>>>();
    k_unzip<<<256, 256, 8192 * 8 + 128 * 8 + 2304 * 4>>>(unzip_w, unzip_b, out);
}

// round 13
// speedup vs baseline: 1.0372x; 1.0372x over previous
#include <cuda_runtime.h>
#include <math.h>

// ------------------------------ scratch (device globals; allocation-free) ---
__device__ float g_conv1[2 * 64 * 512 * 512];   // 128 MB (style, content)
__device__ float g_conv2[2 * 32 * 256 * 256];   // 16 MB
__device__ float g_ff[2 * 16 * 128 * 128];      // conv3 outputs (style, content)
__device__ float g_X[64 * 65536];               // compressed features (uncentered)
__device__ float g_trans[64 * 65536];           // transformed features
__device__ unsigned short g_packed_c[65536];
__device__ unsigned short g_packed_s[65536];
__device__ int g_partial[256][36];              // per-block mask counts
__device__ int g_cnt_s256[9];
__device__ int g_active[9];
__device__ int g_gidx[2 * 9 * 16384];
__device__ int g_gN[2 * 9];
__device__ float g_pooled[2 * 9 * 4096];
__device__ float g_mats[2 * 9 * 4096];      // [0..8]=style sM, [9..17]=content cM
__device__ float g_T[9 * 4096];
__device__ float g_rowsum[64];
__device__ float g_xmean[64];
__device__ float g_ssum[9 * 256];
__device__ float g_smean[9 * 256];
__device__ int g_reg[65536];

// ------------------------------ packed f32x2 helpers ------------------------
__device__ __forceinline__ unsigned long long pk2(float lo, float hi) {
    unsigned long long r;
    asm("mov.b64 %0, {%1, %2};" : "=l"(r) : "f"(lo), "f"(hi));
    return r;
}
__device__ __forceinline__ unsigned long long fma2(unsigned long long a,
                                                   unsigned long long b,
                                                   unsigned long long c) {
    unsigned long long d;
    asm("fma.rn.f32x2 %0, %1, %2, %3;" : "=l"(d) : "l"(a), "l"(b), "l"(c));
    return d;
}
__device__ __forceinline__ void upk2(unsigned long long v, float& lo, float& hi) {
    asm("mov.b64 {%0, %1}, %2;" : "=f"(lo), "=f"(hi) : "l"(v));
}

// ------------------------------------------------------ conv body (shared) ---
// 3x3, stride 2, pad 1.  16 x TH output tile.  Intra-warp oc split:
//   px2 = tid&7, ocg = (tid>>3)%OCG, pyt = tid/(8*OCG)
template <int IC, int OC, int ICB, int OCT, int TH, bool RELU>
__device__ __forceinline__ void conv_body(
    char* smbase, int bx, int by,
    const float* __restrict__ in, const float* __restrict__ w,
    const float* __restrict__ bias, float* __restrict__ out,
    int inH, int inW) {
    constexpr int OCG = OC / OCT;
    constexpr int PAIRS = 8 * TH;
    constexpr int PYT = 32 / OCG;          // py-thread slots (256/(8*OCG))
    constexpr int PH = PAIRS / (8 * PYT);  // pair-rows per thread
    constexpr int ROWS = 2 * TH + 1;
    static_assert(PH >= 1, "tile too small");

    float* s_in = reinterpret_cast<float*>(smbase);                 // [ICB][ROWS][36]
    unsigned long long* s_w2 = reinterpret_cast<unsigned long long*>(
        smbase + ICB * ROWS * 36 * 4);                              // [ICB][9][OC]

    const int tid = threadIdx.x;
    const int px2 = tid & 7;
    const int ocg = (tid >> 3) % OCG;
    const int pyt = tid / (8 * OCG);
    const int px = px2 * 2;
    const int py = pyt * PH;
    const int outH = inH >> 1, outW = inW >> 1;
    const int ox0 = bx * 16, oy0 = by * TH;

    unsigned long long acc[OCT][PH];
    #pragma unroll
    for (int o = 0; o < OCT; o++) {
        float b = bias[ocg * OCT + o];
        #pragma unroll
        for (int ph = 0; ph < PH; ph++) acc[o][ph] = pk2(b, b);
    }

    for (int c0 = 0; c0 < IC; c0 += ICB) {
        __syncthreads();
        for (int idx = tid; idx < ICB * ROWS * 33; idx += 256) {
            int c = idx / (ROWS * 33), r = idx % (ROWS * 33), yy = r / 33, xx = r % 33;
            int iy = 2 * oy0 - 1 + yy, ix = 2 * ox0 - 1 + xx;
            float v = 0.f;
            if (iy >= 0 && iy < inH && ix >= 0 && ix < inW)
                v = in[((size_t)(c0 + c) * inH + iy) * inW + ix];
            s_in[(c * ROWS + yy) * 36 + xx] = v;
        }
        for (int idx = tid; idx < ICB * 9 * OC; idx += 256) {
            int c = idx / (9 * OC), r = idx % (9 * OC), k = r / OC, o = r % OC;
            float wv = w[(o * IC + c0 + c) * 9 + k];
            s_w2[idx] = pk2(wv, wv);
        }
        __syncthreads();
        #pragma unroll
        for (int c = 0; c < ICB; c++)
            #pragma unroll
            for (int ky = 0; ky < 3; ky++) {
                // hoisted row loads: 6 floats per ph via LDS.128 + LDS.64
                float4 v03[PH];
                float2 v45[PH];
                #pragma unroll
                for (int ph = 0; ph < PH; ph++) {
                    const float* rp = &s_in[(c * ROWS + 2 * (py + ph) + ky) * 36 + 2 * px];
                    v03[ph] = *reinterpret_cast<const float4*>(rp);
                    v45[ph] = *reinterpret_cast<const float2*>(rp + 4);
                }
                #pragma unroll
                for (int kx = 0; kx < 3; kx++) {
                    unsigned long long iv[PH];
                    #pragma unroll
                    for (int ph = 0; ph < PH; ph++)
                        iv[ph] = (kx == 0) ? pk2(v03[ph].x, v03[ph].z)
                               : (kx == 1) ? pk2(v03[ph].y, v03[ph].w)
                                           : pk2(v03[ph].z, v45[ph].x);
                    const ulonglong2* wp = reinterpret_cast<const ulonglong2*>(
                        &s_w2[(c * 9 + ky * 3 + kx) * OC + ocg * OCT]);
                    #pragma unroll
                    for (int q = 0; q < OCT / 2; q++) {
                        ulonglong2 wv = wp[q];
                        #pragma unroll
                        for (int ph = 0; ph < PH; ph++) {
                            acc[2 * q][ph] = fma2(wv.x, iv[ph], acc[2 * q][ph]);
                            acc[2 * q + 1][ph] = fma2(wv.y, iv[ph], acc[2 * q + 1][ph]);
                        }
                    }
                }
            }
    }
    #pragma unroll
    for (int o = 0; o < OCT; o++) {
        int oc = ocg * OCT + o;
        #pragma unroll
        for (int ph = 0; ph < PH; ph++) {
            float lo, hi;
            upk2(acc[o][ph], lo, hi);
            if (RELU) { lo = fmaxf(lo, 0.f); hi = fmaxf(hi, 0.f); }
            int oy = oy0 + py + ph, ox = ox0 + px;
            float2* op = reinterpret_cast<float2*>(&out[((size_t)oc * outH + oy) * outW + ox]);
            *op = make_float2(lo, hi);
        }
    }
}

// ------------------------------------------------- init body (16 blocks) ---
__device__ void init_body(int blk, const float* __restrict__ sfcb,
                          const float* __restrict__ cfcb) {
    int t = blk * 256 + threadIdx.x;              // 0..4095
    float sv = sfcb[t], cv = cfcb[t];
    #pragma unroll
    for (int i = 0; i < 9; i++) {
        g_mats[i * 4096 + t] = sv;
        g_mats[(9 + i) * 4096 + t] = cv;
        g_pooled[i * 4096 + t] = 0.f;
        g_pooled[(9 + i) * 4096 + t] = 0.f;
    }
    if (t < 64) g_rowsum[t] = 0.f;
    if (t < 2304) g_ssum[t] = 0.f;
}

// --------------------- masks body (256 blocks; per-block partial counts) ---
__device__ void masks_body(int blk, const int* __restrict__ cm,
                           const int* __restrict__ smk, int* s_cnt) {
    int tid = threadIdx.x;
    if (tid < 36) s_cnt[tid] = 0;
    __syncthreads();
    int p = blk * 256 + tid;
    int y = p >> 8, x = p & 255;
    int even = ((y & 1) == 0) && ((x & 1) == 0);
    unsigned pc = 0, ps = 0;
    #pragma unroll
    for (int i = 0; i < 9; i++) {
        int cb = (cm[i * 65536 + p] == 1);
        int sb = (smk[i * 65536 + p] == 1);
        if (cb) pc |= 1u << i;
        if (sb) ps |= 1u << i;
        unsigned bc = __ballot_sync(0xffffffffu, cb);
        unsigned bs = __ballot_sync(0xffffffffu, sb);
        unsigned bc1 = __ballot_sync(0xffffffffu, cb && even);
        unsigned bs1 = __ballot_sync(0xffffffffu, sb && even);
        if ((tid & 31) == 0) {
            atomicAdd(&s_cnt[i], __popc(bc));
            atomicAdd(&s_cnt[9 + i], __popc(bs));
            atomicAdd(&s_cnt[18 + i], __popc(bc1));
            atomicAdd(&s_cnt[27 + i], __popc(bs1));
        }
    }
    g_packed_c[p] = (unsigned short)pc;
    g_packed_s[p] = (unsigned short)ps;
    __syncthreads();
    if (tid < 36) g_partial[blk][tid] = s_cnt[tid];
}

// -------- compress half: X[o-half] = compress_w @ cF + b, 32 oc per block ---
__device__ void compress_half(char* smbase, int blk, const float* __restrict__ cF,
                              const float* __restrict__ cw, const float* __restrict__ cb) {
    unsigned long long* s_w = reinterpret_cast<unsigned long long*>(smbase); // [64][16]
    int tid = threadIdx.x;
    int p = (blk >> 1) * 256 + tid;
    int o2base = (blk & 1) * 16;
    unsigned long long acc[16];
    #pragma unroll
    for (int o2 = 0; o2 < 16; o2++) {
        int og = o2base + o2;
        acc[o2] = pk2(cb[2 * og], cb[2 * og + 1]);
    }
    for (int c0 = 0; c0 < 256; c0 += 64) {
        __syncthreads();
        for (int idx = tid; idx < 1024; idx += 256) {
            int c = idx >> 4, o2 = idx & 15;
            int og = o2base + o2;
            s_w[idx] = pk2(cw[(2 * og) * 256 + c0 + c],
                           cw[(2 * og + 1) * 256 + c0 + c]);
        }
        __syncthreads();
        for (int c = 0; c < 64; c++) {
            float v = cF[(c0 + c) * 65536 + p];
            unsigned long long vp = pk2(v, v);
            const ulonglong2* wq = reinterpret_cast<const ulonglong2*>(&s_w[c * 16]);
            #pragma unroll
            for (int q = 0; q < 8; q++) {
                ulonglong2 wv = wq[q];
                acc[2 * q] = fma2(wv.x, vp, acc[2 * q]);
                acc[2 * q + 1] = fma2(wv.y, vp, acc[2 * q + 1]);
            }
        }
    }
    int lane = tid & 31;
    #pragma unroll
    for (int o2 = 0; o2 < 16; o2++) {
        int og = o2base + o2;
        float lo, hi;
        upk2(acc[o2], lo, hi);
        g_X[(2 * og) * 65536 + p] = lo;
        g_X[(2 * og + 1) * 65536 + p] = hi;
        float a = lo, b = hi;
        a += __shfl_down_sync(0xffffffffu, a, 16);
        b += __shfl_down_sync(0xffffffffu, b, 16);
        a += __shfl_down_sync(0xffffffffu, a, 8);
        b += __shfl_down_sync(0xffffffffu, b, 8);
        a += __shfl_down_sync(0xffffffffu, a, 4);
        b += __shfl_down_sync(0xffffffffu, b, 4);
        a += __shfl_down_sync(0xffffffffu, a, 2);
        b += __shfl_down_sync(0xffffffffu, b, 2);
        a += __shfl_down_sync(0xffffffffu, a, 1);
        b += __shfl_down_sync(0xffffffffu, b, 1);
        if (lane == 0) {
            atomicAdd(&g_rowsum[2 * og], a);
            atomicAdd(&g_rowsum[2 * og + 1], b);
        }
    }
}

// --------------------- per-region style channel sums (512 blocks, 2/chan) ---
__device__ void stylesum_body(int blk, const float* __restrict__ sF) {
    int tid = threadIdx.x;
    int c = blk >> 1;
    int base = (blk & 1) * 32768;
    float acc[9];
    #pragma unroll
    for (int i = 0; i < 9; i++) acc[i] = 0.f;
    const float* fc = sF + c * 65536;
    for (int k = 0; k < 128; k++) {
        int p = base + k * 256 + tid;
        float v = fc[p];
        unsigned bits = g_packed_s[p];
        #pragma unroll
        for (int i = 0; i < 9; i++)
            acc[i] += ((bits >> i) & 1) ? v : 0.f;
    }
    int lane = tid & 31;
    #pragma unroll
    for (int i = 0; i < 9; i++) {
        float v = acc[i];
        v += __shfl_down_sync(0xffffffffu, v, 16);
        v += __shfl_down_sync(0xffffffffu, v, 8);
        v += __shfl_down_sync(0xffffffffu, v, 4);
        v += __shfl_down_sync(0xffffffffu, v, 2);
        v += __shfl_down_sync(0xffffffffu, v, 1);
        if (lane == 0) atomicAdd(&g_ssum[i * 256 + c], v);
    }
}

// ------------- FAT 1: conv1 (4096 blocks) + masks (256) + init (16) ---------
__global__ __launch_bounds__(256, 3)
void k_fat1(const float* __restrict__ style, const float* __restrict__ content,
            const float* __restrict__ w1s, const float* __restrict__ w1c,
            const float* __restrict__ b1s, const float* __restrict__ b1c,
            const int* __restrict__ cm, const int* __restrict__ smk,
            const float* __restrict__ sfcb, const float* __restrict__ cfcb) {
    __shared__ __align__(16) char sm[3 * 17 * 36 * 4 + 3 * 9 * 64 * 8];  // 21168
    int b = blockIdx.x;
    if (b < 16) {
        init_body(b, sfcb, cfcb);
    } else if (b < 272) {
        masks_body(b - 16, cm, smk, reinterpret_cast<int*>(sm));
    } else {
        int bb = b - 272;
        int bx = bb & 31, by = (bb >> 5) & 63, img = bb >> 11;
        conv_body<3, 64, 3, 8, 8, true>(
            sm, bx, by, img ? content : style, img ? w1c : w1s,
            img ? b1c : b1s, &g_conv1[(size_t)img * 64 * 512 * 512], 1024, 1024);
    }
}

// ---- FAT 2: conv2 (512) + compress (512) interleaved first, stylesum last --
// LPT ordering: long conv blocks start early (mixed with compress for pipe
// diversity); shortest role (stylesum) fills the tail.
__global__ __launch_bounds__(256, 3)
void k_fat2(const float* __restrict__ w2s, const float* __restrict__ w2c,
            const float* __restrict__ b2s, const float* __restrict__ b2c,
            const float* __restrict__ cF, const float* __restrict__ cw,
            const float* __restrict__ cb, const float* __restrict__ sF) {
    __shared__ __align__(16) char sm[4 * 33 * 36 * 4 + 4 * 9 * 32 * 8];  // 28224
    int b = blockIdx.x;
    if (b < 1024) {
        int idx = b >> 1;
        if ((b & 1) == 0) {
            int bx = idx & 15, by = (idx >> 4) & 15, img = idx >> 8;
            conv_body<64, 32, 4, 8, 16, true>(
                sm, bx, by, &g_conv1[(size_t)img * 64 * 512 * 512],
                img ? w2c : w2s, img ? b2c : b2s,
                &g_conv2[(size_t)img * 32 * 256 * 256], 512, 512);
        } else {
            compress_half(sm, idx, cF, cw, cb);
        }
    } else {
        stylesum_body(b - 1024, sF);
    }
}

// ---------------------------------------------------------------- conv3 ---
__global__ __launch_bounds__(256, 2)
void k_conv3(const float* __restrict__ w3s, const float* __restrict__ w3c,
             const float* __restrict__ b3s, const float* __restrict__ b3c) {
    __shared__ __align__(16) char sm[4 * 33 * 36 * 4 + 4 * 9 * 16 * 8];  // 23616
    int img = blockIdx.z;
    conv_body<32, 16, 4, 8, 16, false>(
        sm, blockIdx.x, blockIdx.y, &g_conv2[(size_t)img * 32 * 256 * 256],
        img ? w3c : w3s, img ? b3c : b3s,
        &g_ff[(size_t)img * 16 * 128 * 128], 256, 256);
}

// ------------ mask compaction (blocks 0-17) + active/counts (block 18) ------
__global__ void k_gather() {
    int tid = threadIdx.x, lane = tid & 31, wid = tid >> 5;
    if (blockIdx.x == 18) {                    // active flags + s256 counts
        __shared__ int sums[36];
        if (tid < 36) {
            int s = 0;
            for (int b = 0; b < 256; b++) s += g_partial[b][tid];
            sums[tid] = s;
        }
        __syncthreads();
        if (tid < 9) {
            g_active[tid] = (sums[tid] >= 10) && (sums[9 + tid] >= 10) &&
                            (sums[18 + tid] >= 10) && (sums[27 + tid] >= 10);
            g_cnt_s256[tid] = sums[9 + tid];
        }
        return;
    }
    int img = blockIdx.x / 9, i = blockIdx.x % 9;
    const unsigned short* pk = (img == 0) ? g_packed_s : g_packed_c;

    __shared__ unsigned s_words[512];
    __shared__ int s_wsum[8];

    for (int widx = wid; widx < 512; widx += 8) {
        int pos = widx * 32 + lane;
        int yy = pos >> 7, xx = pos & 127;
        int p = (yy << 9) | (xx << 1);          // (2y)*256 + 2x
        unsigned b = __ballot_sync(0xffffffffu, (pk[p] >> i) & 1);
        if (lane == 0) s_words[widx] = b;
    }
    __syncthreads();

    unsigned w0 = s_words[2 * tid], w1 = s_words[2 * tid + 1];
    int c2 = __popc(w0) + __popc(w1);
    int v = c2;
    #pragma unroll
    for (int d = 1; d < 32; d <<= 1) {
        int n = __shfl_up_sync(0xffffffffu, v, d);
        if (lane >= d) v += n;
    }
    if (lane == 31) s_wsum[wid] = v;
    __syncthreads();
    if (wid == 0 && lane < 8) {
        int t = s_wsum[lane];
        #pragma unroll
        for (int d = 1; d < 8; d <<= 1) {
            int n = __shfl_up_sync(0xffu, t, d);
            if (lane >= d) t += n;
        }
        s_wsum[lane] = t;
    }
    __syncthreads();
    int base = v - c2 + (wid ? s_wsum[wid - 1] : 0);   // exclusive prefix

    int* gx = g_gidx + (img * 9 + i) * 16384;
    int o = base, pb = tid * 64;
    unsigned m = w0;
    while (m) { int b = __ffs(m) - 1; m &= m - 1; gx[o++] = pb + b; }
    m = w1; pb += 32;
    while (m) { int b = __ffs(m) - 1; m &= m - 1; gx[o++] = pb + b; }
    if (tid == 255) g_gN[img * 9 + i] = base + c2;
}

// ------------------------- adaptive max pool 256: block per (img,reg,chan) ---
__global__ void k_pool() {
    int img = blockIdx.x / 9, i = blockIdx.x % 9, c = blockIdx.y;
    int N = g_gN[img * 9 + i];
    if (N < 10) return;
    int j = threadIdx.x;                       // bin 0..255
    int s = (j * N) >> 8;
    int e = ((j + 1) * N + 255) >> 8;
    const float* fc = g_ff + img * 16 * 16384 + c * 16384;
    const int* gx = g_gidx + (img * 9 + i) * 16384;
    float m = -3.4e38f;
    for (int r = s; r < e; r++) m = fmaxf(m, fc[gx[r]]);
    g_pooled[(img * 9 + i) * 4096 + c * 256 + j] = m;
}

// ------ FC: mats[img][i][r] += fcw[r,:] @ pooled[img][i]  (coalesced k) -----
__global__ __launch_bounds__(256, 2)
void k_fc(const float* __restrict__ sfcw, const float* __restrict__ cfcw) {
    int img = blockIdx.y;
    const float* fcw = (img == 0) ? sfcw : cfcw;
    __shared__ float sp[9][1024];
    int tid = threadIdx.x, lane = tid & 31, wid = tid >> 5;
    int r0 = blockIdx.x * 32 + wid * 4;
    float acc[4][9];
    #pragma unroll
    for (int rr = 0; rr < 4; rr++)
        #pragma unroll
        for (int i = 0; i < 9; i++) acc[rr][i] = 0.f;

    for (int kc = 0; kc < 4096; kc += 1024) {
        __syncthreads();
        for (int idx = tid * 4; idx < 9216; idx += 1024) {
            int i = idx >> 10, kk = idx & 1023;
            *(float4*)&sp[i][kk] =
                *(const float4*)&g_pooled[(img * 9 + i) * 4096 + kc + kk];
        }
        __syncthreads();
        for (int kk = lane * 4; kk < 1024; kk += 128) {
            float4 p4[9];
            #pragma unroll
            for (int i = 0; i < 9; i++) p4[i] = *(const float4*)&sp[i][kk];
            #pragma unroll
            for (int rr = 0; rr < 4; rr++) {
                float4 w4 = *(const float4*)&fcw[(size_t)(r0 + rr) * 4096 + kc + kk];
                #pragma unroll
                for (int i = 0; i < 9; i++)
                    acc[rr][i] += w4.x * p4[i].x + w4.y * p4[i].y +
                                  w4.z * p4[i].z + w4.w * p4[i].w;
            }
        }
    }
    #pragma unroll
    for (int rr = 0; rr < 4; rr++)
        #pragma unroll
        for (int i = 0; i < 9; i++) {
            float v = acc[rr][i];
            #pragma unroll
            for (int off = 16; off; off >>= 1)
                v += __shfl_xor_sync(0xffffffffu, v, off);
            if (lane == 0) g_mats[(img * 9 + i) * 4096 + r0 + rr] += v;
        }
}

// --------------- T_i = sM_i @ cM_i (blocks 0-8) + finalize (block 9) --------
__global__ void k_T() {
    if (blockIdx.x == 9) {                     // xmean + smean finalize
        for (int t = threadIdx.x; t < 2304; t += 256) {
            if (t < 64) g_xmean[t] = g_rowsum[t] * (1.f / 65536.f);
            int i = t >> 8;
            int n = g_cnt_s256[i];
            g_smean[t] = (n > 0) ? g_ssum[t] / (float)n : 0.f;
        }
        return;
    }
    int i = blockIdx.x;
    if (!g_active[i]) return;
    __shared__ float sA[4096], sB[4096];
    for (int idx = threadIdx.x; idx < 4096; idx += 256) {
        sA[idx] = g_mats[i * 4096 + idx];          // sM
        sB[idx] = g_mats[(9 + i) * 4096 + idx];    // cM
    }
    __syncthreads();
    for (int idx = threadIdx.x; idx < 4096; idx += 256) {
        int o = idx >> 6, n = idx & 63;
        float a = 0.f;
        #pragma unroll 16
        for (int k = 0; k < 64; k++) a += sA[o * 64 + k] * sB[k * 64 + n];
        g_T[i * 4096 + idx] = a;
    }
}

// --------------- trans = (region ? T_reg @ Xc : Xc), last active region wins ---
__global__ void k_trans() {
    extern __shared__ float sT[];              // 9 * 4100 floats
    __shared__ float sxm[64];
    __shared__ int sact[9];
    int tid = threadIdx.x;
    for (int idx = tid; idx < 9 * 4096; idx += 256)
        sT[(idx >> 12) * 4100 + (idx & 4095)] = g_T[idx];
    if (tid < 64) sxm[tid] = g_xmean[tid];
    if (tid < 9) sact[tid] = g_active[tid];
    __syncthreads();
    int p = blockIdx.x * 256 + tid;
    unsigned bits = g_packed_c[p];
    int reg = -1;
    #pragma unroll
    for (int i = 8; i >= 0; i--)
        if (reg < 0 && sact[i] && ((bits >> i) & 1)) reg = i;
    float x[64];
    #pragma unroll
    for (int o = 0; o < 64; o++) x[o] = g_X[o * 65536 + p] - sxm[o];
    if (reg >= 0) {
        const float* T = &sT[reg * 4100];
        for (int o = 0; o < 64; o++) {
            const float4* t4 = reinterpret_cast<const float4*>(&T[o * 64]);
            float a0 = 0.f, a1 = 0.f, a2 = 0.f, a3 = 0.f;
            #pragma unroll
            for (int q = 0; q < 16; q++) {
                float4 tv = t4[q];
                a0 = fmaf(tv.x, x[4 * q], a0);
                a1 = fmaf(tv.y, x[4 * q + 1], a1);
                a2 = fmaf(tv.z, x[4 * q + 2], a2);
                a3 = fmaf(tv.w, x[4 * q + 3], a3);
            }
            g_trans[o * 65536 + p] = (a0 + a1) + (a2 + a3);
        }
    } else {
        #pragma unroll
        for (int o = 0; o < 64; o++) g_trans[o * 65536 + p] = x[o];
    }
    g_reg[p] = reg;
}

// ------- out = unzip_w @ trans + unzip_b + smean[region]  (f32x2 oc pairs) ---
__global__ __launch_bounds__(256, 2)
void k_unzip(const float* __restrict__ uw, const float* __restrict__ ub,
             float* __restrict__ out) {
    extern __shared__ unsigned long long dynsm[];
    unsigned long long* s_w2 = dynsm;              // [c][o2] = 64*128 u64
    unsigned long long* s_b2 = dynsm + 8192;       // [128]
    float* s_m = (float*)(dynsm + 8192 + 128);     // [9*256]
    int tid = threadIdx.x;
    for (int idx = tid; idx < 8192; idx += 256) {
        int c = idx >> 7, o2 = idx & 127;
        s_w2[idx] = pk2(uw[(2 * o2) * 64 + c], uw[(2 * o2 + 1) * 64 + c]);
    }
    if (tid < 128) s_b2[tid] = pk2(ub[2 * tid], ub[2 * tid + 1]);
    for (int idx = tid; idx < 2304; idx += 256) s_m[idx] = g_smean[idx];
    __syncthreads();
    int p = blockIdx.x * 256 + tid;
    float tr[64];
    #pragma unroll
    for (int c = 0; c < 64; c++) tr[c] = g_trans[c * 65536 + p];
    int reg = g_reg[p];
    #pragma unroll 1
    for (int t = 0; t < 8; t++) {                  // 8 tiles of 16 oc-pairs
        unsigned long long acc[16];
        #pragma unroll
        for (int q = 0; q < 16; q++) acc[q] = s_b2[t * 16 + q];
        #pragma unroll 8
        for (int c = 0; c < 64; c++) {
            unsigned long long xd = pk2(tr[c], tr[c]);
            const ulonglong2* wp =
                reinterpret_cast<const ulonglong2*>(&s_w2[c * 128 + t * 16]);
            #pragma unroll
            for (int q2 = 0; q2 < 8; q2++) {
                ulonglong2 wv = wp[q2];
                acc[2 * q2] = fma2(wv.x, xd, acc[2 * q2]);
                acc[2 * q2 + 1] = fma2(wv.y, xd, acc[2 * q2 + 1]);
            }
        }
        #pragma unroll
        for (int q = 0; q < 16; q++) {
            float lo, hi;
            upk2(acc[q], lo, hi);
            int o = (t * 16 + q) * 2;
            if (reg >= 0) { lo += s_m[reg * 256 + o]; hi += s_m[reg * 256 + o + 1]; }
            out[(size_t)o * 65536 + p] = lo;
            out[(size_t)(o + 1) * 65536 + p] = hi;
        }
    }
}

// ---------------------------------------------------------------- launch ---
extern "C" void kernel_launch(void* const* d_in, const int* in_sizes, int n_in,
                              void* d_out, int out_size) {
    (void)in_sizes; (void)n_in; (void)out_size;
    const float* cF         = (const float*)d_in[0];
    const float* sF         = (const float*)d_in[1];
    const float* content    = (const float*)d_in[2];
    const float* style      = (const float*)d_in[3];
    const int*   cmasks     = (const int*)d_in[4];
    const int*   smasks     = (const int*)d_in[5];
    const float* compress_w = (const float*)d_in[6];
    const float* compress_b = (const float*)d_in[7];
    const float* unzip_w    = (const float*)d_in[8];
    const float* unzip_b    = (const float*)d_in[9];
    const float* s_w1 = (const float*)d_in[10]; const float* s_b1 = (const float*)d_in[11];
    const float* s_w2 = (const float*)d_in[12]; const float* s_b2 = (const float*)d_in[13];
    const float* s_w3 = (const float*)d_in[14]; const float* s_b3 = (const float*)d_in[15];
    const float* s_fcw = (const float*)d_in[16]; const float* s_fcb = (const float*)d_in[17];
    const float* c_w1 = (const float*)d_in[18]; const float* c_b1 = (const float*)d_in[19];
    const float* c_w2 = (const float*)d_in[20]; const float* c_b2 = (const float*)d_in[21];
    const float* c_w3 = (const float*)d_in[22]; const float* c_b3 = (const float*)d_in[23];
    const float* c_fcw = (const float*)d_in[24]; const float* c_fcb = (const float*)d_in[25];
    float* out = (float*)d_out;

    // opt-in dynamic smem (idempotent; host API, capture-safe)
    cudaFuncSetAttribute(k_trans, cudaFuncAttributeMaxDynamicSharedMemorySize, 9 * 4100 * 4);
    cudaFuncSetAttribute(k_unzip, cudaFuncAttributeMaxDynamicSharedMemorySize,
                         8192 * 8 + 128 * 8 + 2304 * 4);

    // 1: conv1 + masks + init (independent roles fused)
    k_fat1<<<4368, 256>>>(style, content, s_w1, c_w1, s_b1, c_b1,
                          cmasks, smasks, s_fcb, c_fcb);
    // 2: mask compaction + active flags (needs masks partials)
    k_gather<<<19, 256>>>();
    // 3: (slot kept so fat2 stays the profiled 4th launch) — conv3 grid is
    //    empty-dependency-free only after fat2; use a tiny no-dep kernel? No:
    //    launch pool's dependencies later.  Here: nothing needed; fat2 next.
    // 4 <- profiled: conv2 + compress interleaved, stylesum tail (LPT order)
    k_fat2<<<1536, 256>>>(s_w2, c_w2, s_b2, c_b2, cF, compress_w, compress_b, sF);
    // 5: conv3
    k_conv3<<<dim3(8, 8, 2), 256>>>(s_w3, c_w3, s_b3, c_b3);
    // 6-8: pool, fc, T+finalize
    k_pool<<<dim3(18, 16), 256>>>();
    k_fc<<<dim3(128, 2), 256>>>(s_fcw, c_fcw);
    k_T<<<10, 256>>>();
    // 9-10: trans, unzip
    k_trans<<<256, 256, 9 * 4100 * 4>>>();
    k_unzip<<<256, 256, 8192 * 8 + 128 * 8 + 2304 * 4>>>(unzip_w, unzip_b, out);
}

// round 14
// speedup vs baseline: 1.0379x; 1.0007x over previous
#include <cuda_runtime.h>
#include <math.h>

// ------------------------------ scratch (device globals; allocation-free) ---
__device__ float g_conv1[2 * 64 * 512 * 512];   // 128 MB (style, content)
__device__ float g_conv2[2 * 32 * 256 * 256];   // 16 MB
__device__ float g_ff[2 * 16 * 128 * 128];      // conv3 outputs (style, content)
__device__ float g_X[64 * 65536];               // compressed features (uncentered)
__device__ float g_trans[64 * 65536];           // transformed features
__device__ unsigned short g_packed_c[65536];
__device__ unsigned short g_packed_s[65536];
__device__ int g_partial[256][36];              // per-block mask counts
__device__ int g_cnt_s256[9];
__device__ int g_active[9];
__device__ int g_gidx[2 * 9 * 16384];
__device__ int g_gN[2 * 9];
__device__ float g_pooled[2 * 9 * 4096];
__device__ float g_mats[2 * 9 * 4096];      // [0..8]=style sM, [9..17]=content cM
__device__ float g_T[9 * 4096];
__device__ float g_rowsum[64];
__device__ float g_xmean[64];
__device__ float g_ssum[9 * 256];
__device__ float g_smean[9 * 256];
__device__ int g_reg[65536];

// ------------------------------ packed f32x2 helpers ------------------------
__device__ __forceinline__ unsigned long long pk2(float lo, float hi) {
    unsigned long long r;
    asm("mov.b64 %0, {%1, %2};" : "=l"(r) : "f"(lo), "f"(hi));
    return r;
}
__device__ __forceinline__ unsigned long long fma2(unsigned long long a,
                                                   unsigned long long b,
                                                   unsigned long long c) {
    unsigned long long d;
    asm("fma.rn.f32x2 %0, %1, %2, %3;" : "=l"(d) : "l"(a), "l"(b), "l"(c));
    return d;
}
__device__ __forceinline__ void upk2(unsigned long long v, float& lo, float& hi) {
    asm("mov.b64 {%0, %1}, %2;" : "=f"(lo), "=f"(hi) : "l"(v));
}

// ------------------------------------------------------ conv body (shared) ---
// 3x3, stride 2, pad 1.  16 x TH output tile.  Intra-warp oc split:
//   px2 = tid&7, ocg = (tid>>3)%OCG, pyt = tid/(8*OCG)
template <int IC, int OC, int ICB, int OCT, int TH, bool RELU>
__device__ __forceinline__ void conv_body(
    char* smbase, int bx, int by,
    const float* __restrict__ in, const float* __restrict__ w,
    const float* __restrict__ bias, float* __restrict__ out,
    int inH, int inW) {
    constexpr int OCG = OC / OCT;
    constexpr int PAIRS = 8 * TH;
    constexpr int PYT = 32 / OCG;          // py-thread slots (256/(8*OCG))
    constexpr int PH = PAIRS / (8 * PYT);  // pair-rows per thread
    constexpr int ROWS = 2 * TH + 1;
    static_assert(PH >= 1, "tile too small");

    float* s_in = reinterpret_cast<float*>(smbase);                 // [ICB][ROWS][36]
    unsigned long long* s_w2 = reinterpret_cast<unsigned long long*>(
        smbase + ICB * ROWS * 36 * 4);                              // [ICB][9][OC]

    const int tid = threadIdx.x;
    const int px2 = tid & 7;
    const int ocg = (tid >> 3) % OCG;
    const int pyt = tid / (8 * OCG);
    const int px = px2 * 2;
    const int py = pyt * PH;
    const int outH = inH >> 1, outW = inW >> 1;
    const int ox0 = bx * 16, oy0 = by * TH;

    unsigned long long acc[OCT][PH];
    #pragma unroll
    for (int o = 0; o < OCT; o++) {
        float b = bias[ocg * OCT + o];
        #pragma unroll
        for (int ph = 0; ph < PH; ph++) acc[o][ph] = pk2(b, b);
    }

    for (int c0 = 0; c0 < IC; c0 += ICB) {
        __syncthreads();
        for (int idx = tid; idx < ICB * ROWS * 33; idx += 256) {
            int c = idx / (ROWS * 33), r = idx % (ROWS * 33), yy = r / 33, xx = r % 33;
            int iy = 2 * oy0 - 1 + yy, ix = 2 * ox0 - 1 + xx;
            float v = 0.f;
            if (iy >= 0 && iy < inH && ix >= 0 && ix < inW)
                v = in[((size_t)(c0 + c) * inH + iy) * inW + ix];
            s_in[(c * ROWS + yy) * 36 + xx] = v;
        }
        for (int idx = tid; idx < ICB * 9 * OC; idx += 256) {
            int c = idx / (9 * OC), r = idx % (9 * OC), k = r / OC, o = r % OC;
            float wv = w[(o * IC + c0 + c) * 9 + k];
            s_w2[idx] = pk2(wv, wv);
        }
        __syncthreads();
        #pragma unroll
        for (int c = 0; c < ICB; c++)
            #pragma unroll
            for (int ky = 0; ky < 3; ky++) {
                // hoisted row loads: 6 floats per ph via LDS.128 + LDS.64
                float4 v03[PH];
                float2 v45[PH];
                #pragma unroll
                for (int ph = 0; ph < PH; ph++) {
                    const float* rp = &s_in[(c * ROWS + 2 * (py + ph) + ky) * 36 + 2 * px];
                    v03[ph] = *reinterpret_cast<const float4*>(rp);
                    v45[ph] = *reinterpret_cast<const float2*>(rp + 4);
                }
                #pragma unroll
                for (int kx = 0; kx < 3; kx++) {
                    unsigned long long iv[PH];
                    #pragma unroll
                    for (int ph = 0; ph < PH; ph++)
                        iv[ph] = (kx == 0) ? pk2(v03[ph].x, v03[ph].z)
                               : (kx == 1) ? pk2(v03[ph].y, v03[ph].w)
                                           : pk2(v03[ph].z, v45[ph].x);
                    const ulonglong2* wp = reinterpret_cast<const ulonglong2*>(
                        &s_w2[(c * 9 + ky * 3 + kx) * OC + ocg * OCT]);
                    #pragma unroll
                    for (int q = 0; q < OCT / 2; q++) {
                        ulonglong2 wv = wp[q];
                        #pragma unroll
                        for (int ph = 0; ph < PH; ph++) {
                            acc[2 * q][ph] = fma2(wv.x, iv[ph], acc[2 * q][ph]);
                            acc[2 * q + 1][ph] = fma2(wv.y, iv[ph], acc[2 * q + 1][ph]);
                        }
                    }
                }
            }
    }
    #pragma unroll
    for (int o = 0; o < OCT; o++) {
        int oc = ocg * OCT + o;
        #pragma unroll
        for (int ph = 0; ph < PH; ph++) {
            float lo, hi;
            upk2(acc[o][ph], lo, hi);
            if (RELU) { lo = fmaxf(lo, 0.f); hi = fmaxf(hi, 0.f); }
            int oy = oy0 + py + ph, ox = ox0 + px;
            float2* op = reinterpret_cast<float2*>(&out[((size_t)oc * outH + oy) * outW + ox]);
            *op = make_float2(lo, hi);
        }
    }
}

// ------------------------------------------------- init body (16 blocks) ---
__device__ void init_body(int blk, const float* __restrict__ sfcb,
                          const float* __restrict__ cfcb) {
    int t = blk * 256 + threadIdx.x;              // 0..4095
    float sv = sfcb[t], cv = cfcb[t];
    #pragma unroll
    for (int i = 0; i < 9; i++) {
        g_mats[i * 4096 + t] = sv;
        g_mats[(9 + i) * 4096 + t] = cv;
        g_pooled[i * 4096 + t] = 0.f;
        g_pooled[(9 + i) * 4096 + t] = 0.f;
    }
    if (t < 64) g_rowsum[t] = 0.f;
    if (t < 2304) g_ssum[t] = 0.f;
}

// --------------------- masks body (256 blocks; per-block partial counts) ---
__device__ void masks_body(int blk, const int* __restrict__ cm,
                           const int* __restrict__ smk, int* s_cnt) {
    int tid = threadIdx.x;
    if (tid < 36) s_cnt[tid] = 0;
    __syncthreads();
    int p = blk * 256 + tid;
    int y = p >> 8, x = p & 255;
    int even = ((y & 1) == 0) && ((x & 1) == 0);
    unsigned pc = 0, ps = 0;
    #pragma unroll
    for (int i = 0; i < 9; i++) {
        int cb = (cm[i * 65536 + p] == 1);
        int sb = (smk[i * 65536 + p] == 1);
        if (cb) pc |= 1u << i;
        if (sb) ps |= 1u << i;
        unsigned bc = __ballot_sync(0xffffffffu, cb);
        unsigned bs = __ballot_sync(0xffffffffu, sb);
        unsigned bc1 = __ballot_sync(0xffffffffu, cb && even);
        unsigned bs1 = __ballot_sync(0xffffffffu, sb && even);
        if ((tid & 31) == 0) {
            atomicAdd(&s_cnt[i], __popc(bc));
            atomicAdd(&s_cnt[9 + i], __popc(bs));
            atomicAdd(&s_cnt[18 + i], __popc(bc1));
            atomicAdd(&s_cnt[27 + i], __popc(bs1));
        }
    }
    g_packed_c[p] = (unsigned short)pc;
    g_packed_s[p] = (unsigned short)ps;
    __syncthreads();
    if (tid < 36) g_partial[blk][tid] = s_cnt[tid];
}

// -------- compress half: X[o-half] = compress_w @ cF + b, 32 oc per block ---
__device__ void compress_half(char* smbase, int blk, const float* __restrict__ cF,
                              const float* __restrict__ cw, const float* __restrict__ cb) {
    unsigned long long* s_w = reinterpret_cast<unsigned long long*>(smbase); // [64][16]
    int tid = threadIdx.x;
    int p = (blk >> 1) * 256 + tid;
    int o2base = (blk & 1) * 16;
    unsigned long long acc[16];
    #pragma unroll
    for (int o2 = 0; o2 < 16; o2++) {
        int og = o2base + o2;
        acc[o2] = pk2(cb[2 * og], cb[2 * og + 1]);
    }
    for (int c0 = 0; c0 < 256; c0 += 64) {
        __syncthreads();
        for (int idx = tid; idx < 1024; idx += 256) {
            int c = idx >> 4, o2 = idx & 15;
            int og = o2base + o2;
            s_w[idx] = pk2(cw[(2 * og) * 256 + c0 + c],
                           cw[(2 * og + 1) * 256 + c0 + c]);
        }
        __syncthreads();
        for (int c = 0; c < 64; c++) {
            float v = cF[(c0 + c) * 65536 + p];
            unsigned long long vp = pk2(v, v);
            const ulonglong2* wq = reinterpret_cast<const ulonglong2*>(&s_w[c * 16]);
            #pragma unroll
            for (int q = 0; q < 8; q++) {
                ulonglong2 wv = wq[q];
                acc[2 * q] = fma2(wv.x, vp, acc[2 * q]);
                acc[2 * q + 1] = fma2(wv.y, vp, acc[2 * q + 1]);
            }
        }
    }
    int lane = tid & 31;
    #pragma unroll
    for (int o2 = 0; o2 < 16; o2++) {
        int og = o2base + o2;
        float lo, hi;
        upk2(acc[o2], lo, hi);
        g_X[(2 * og) * 65536 + p] = lo;
        g_X[(2 * og + 1) * 65536 + p] = hi;
        float a = lo, b = hi;
        a += __shfl_down_sync(0xffffffffu, a, 16);
        b += __shfl_down_sync(0xffffffffu, b, 16);
        a += __shfl_down_sync(0xffffffffu, a, 8);
        b += __shfl_down_sync(0xffffffffu, b, 8);
        a += __shfl_down_sync(0xffffffffu, a, 4);
        b += __shfl_down_sync(0xffffffffu, b, 4);
        a += __shfl_down_sync(0xffffffffu, a, 2);
        b += __shfl_down_sync(0xffffffffu, b, 2);
        a += __shfl_down_sync(0xffffffffu, a, 1);
        b += __shfl_down_sync(0xffffffffu, b, 1);
        if (lane == 0) {
            atomicAdd(&g_rowsum[2 * og], a);
            atomicAdd(&g_rowsum[2 * og + 1], b);
        }
    }
}

// --------------------- per-region style channel sums (512 blocks, 2/chan) ---
__device__ void stylesum_body(int blk, const float* __restrict__ sF) {
    int tid = threadIdx.x;
    int c = blk >> 1;
    int base = (blk & 1) * 32768;
    float acc[9];
    #pragma unroll
    for (int i = 0; i < 9; i++) acc[i] = 0.f;
    const float* fc = sF + c * 65536;
    for (int k = 0; k < 128; k++) {
        int p = base + k * 256 + tid;
        float v = fc[p];
        unsigned bits = g_packed_s[p];
        #pragma unroll
        for (int i = 0; i < 9; i++)
            acc[i] += ((bits >> i) & 1) ? v : 0.f;
    }
    int lane = tid & 31;
    #pragma unroll
    for (int i = 0; i < 9; i++) {
        float v = acc[i];
        v += __shfl_down_sync(0xffffffffu, v, 16);
        v += __shfl_down_sync(0xffffffffu, v, 8);
        v += __shfl_down_sync(0xffffffffu, v, 4);
        v += __shfl_down_sync(0xffffffffu, v, 2);
        v += __shfl_down_sync(0xffffffffu, v, 1);
        if (lane == 0) atomicAdd(&g_ssum[i * 256 + c], v);
    }
}

// ------------- FAT 1: conv1 (4096 blocks) + masks (256) + init (16) ---------
__global__ __launch_bounds__(256, 3)
void k_fat1(const float* __restrict__ style, const float* __restrict__ content,
            const float* __restrict__ w1s, const float* __restrict__ w1c,
            const float* __restrict__ b1s, const float* __restrict__ b1c,
            const int* __restrict__ cm, const int* __restrict__ smk,
            const float* __restrict__ sfcb, const float* __restrict__ cfcb) {
    __shared__ __align__(16) char sm[3 * 17 * 36 * 4 + 3 * 9 * 64 * 8];  // 21168
    int b = blockIdx.x;
    if (b < 16) {
        init_body(b, sfcb, cfcb);
    } else if (b < 272) {
        masks_body(b - 16, cm, smk, reinterpret_cast<int*>(sm));
    } else {
        int bb = b - 272;
        int bx = bb & 31, by = (bb >> 5) & 63, img = bb >> 11;
        conv_body<3, 64, 3, 8, 8, true>(
            sm, bx, by, img ? content : style, img ? w1c : w1s,
            img ? b1c : b1s, &g_conv1[(size_t)img * 64 * 512 * 512], 1024, 1024);
    }
}

// ---- FAT 2: conv2 (512) + compress (512) interleaved first, stylesum last --
// LPT ordering: long conv blocks start early (mixed with compress for pipe
// diversity); shortest role (stylesum) fills the tail.
__global__ __launch_bounds__(256, 3)
void k_fat2(const float* __restrict__ w2s, const float* __restrict__ w2c,
            const float* __restrict__ b2s, const float* __restrict__ b2c,
            const float* __restrict__ cF, const float* __restrict__ cw,
            const float* __restrict__ cb, const float* __restrict__ sF) {
    __shared__ __align__(16) char sm[4 * 33 * 36 * 4 + 4 * 9 * 32 * 8];  // 28224
    int b = blockIdx.x;
    if (b < 1024) {
        int idx = b >> 1;
        if ((b & 1) == 0) {
            int bx = idx & 15, by = (idx >> 4) & 15, img = idx >> 8;
            conv_body<64, 32, 4, 8, 16, true>(
                sm, bx, by, &g_conv1[(size_t)img * 64 * 512 * 512],
                img ? w2c : w2s, img ? b2c : b2s,
                &g_conv2[(size_t)img * 32 * 256 * 256], 512, 512);
        } else {
            compress_half(sm, idx, cF, cw, cb);
        }
    } else {
        stylesum_body(b - 1024, sF);
    }
}

// ---------------------------------------------------------------- conv3 ---
__global__ __launch_bounds__(256, 2)
void k_conv3(const float* __restrict__ w3s, const float* __restrict__ w3c,
             const float* __restrict__ b3s, const float* __restrict__ b3c) {
    __shared__ __align__(16) char sm[4 * 33 * 36 * 4 + 4 * 9 * 16 * 8];  // 23616
    int img = blockIdx.z;
    conv_body<32, 16, 4, 8, 16, false>(
        sm, blockIdx.x, blockIdx.y, &g_conv2[(size_t)img * 32 * 256 * 256],
        img ? w3c : w3s, img ? b3c : b3s,
        &g_ff[(size_t)img * 16 * 128 * 128], 256, 256);
}

// ------------ mask compaction (blocks 0-17) + active/counts (block 18) ------
__global__ void k_gather() {
    int tid = threadIdx.x, lane = tid & 31, wid = tid >> 5;
    if (blockIdx.x == 18) {                    // active flags + s256 counts
        __shared__ int sums[36];
        if (tid < 36) {
            int s = 0;
            for (int b = 0; b < 256; b++) s += g_partial[b][tid];
            sums[tid] = s;
        }
        __syncthreads();
        if (tid < 9) {
            g_active[tid] = (sums[tid] >= 10) && (sums[9 + tid] >= 10) &&
                            (sums[18 + tid] >= 10) && (sums[27 + tid] >= 10);
            g_cnt_s256[tid] = sums[9 + tid];
        }
        return;
    }
    int img = blockIdx.x / 9, i = blockIdx.x % 9;
    const unsigned short* pk = (img == 0) ? g_packed_s : g_packed_c;

    __shared__ unsigned s_words[512];
    __shared__ int s_wsum[8];

    for (int widx = wid; widx < 512; widx += 8) {
        int pos = widx * 32 + lane;
        int yy = pos >> 7, xx = pos & 127;
        int p = (yy << 9) | (xx << 1);          // (2y)*256 + 2x
        unsigned b = __ballot_sync(0xffffffffu, (pk[p] >> i) & 1);
        if (lane == 0) s_words[widx] = b;
    }
    __syncthreads();

    unsigned w0 = s_words[2 * tid], w1 = s_words[2 * tid + 1];
    int c2 = __popc(w0) + __popc(w1);
    int v = c2;
    #pragma unroll
    for (int d = 1; d < 32; d <<= 1) {
        int n = __shfl_up_sync(0xffffffffu, v, d);
        if (lane >= d) v += n;
    }
    if (lane == 31) s_wsum[wid] = v;
    __syncthreads();
    if (wid == 0 && lane < 8) {
        int t = s_wsum[lane];
        #pragma unroll
        for (int d = 1; d < 8; d <<= 1) {
            int n = __shfl_up_sync(0xffu, t, d);
            if (lane >= d) t += n;
        }
        s_wsum[lane] = t;
    }
    __syncthreads();
    int base = v - c2 + (wid ? s_wsum[wid - 1] : 0);   // exclusive prefix

    int* gx = g_gidx + (img * 9 + i) * 16384;
    int o = base, pb = tid * 64;
    unsigned m = w0;
    while (m) { int b = __ffs(m) - 1; m &= m - 1; gx[o++] = pb + b; }
    m = w1; pb += 32;
    while (m) { int b = __ffs(m) - 1; m &= m - 1; gx[o++] = pb + b; }
    if (tid == 255) g_gN[img * 9 + i] = base + c2;
}

// ------------------------- adaptive max pool 256: block per (img,reg,chan) ---
__global__ void k_pool() {
    int img = blockIdx.x / 9, i = blockIdx.x % 9, c = blockIdx.y;
    int N = g_gN[img * 9 + i];
    if (N < 10) return;
    int j = threadIdx.x;                       // bin 0..255
    int s = (j * N) >> 8;
    int e = ((j + 1) * N + 255) >> 8;
    const float* fc = g_ff + img * 16 * 16384 + c * 16384;
    const int* gx = g_gidx + (img * 9 + i) * 16384;
    float m = -3.4e38f;
    for (int r = s; r < e; r++) m = fmaxf(m, fc[gx[r]]);
    g_pooled[(img * 9 + i) * 4096 + c * 256 + j] = m;
}

// ------ FC: mats[img][i][r] += fcw[r,:] @ pooled[img][i]  (coalesced k) -----
__global__ __launch_bounds__(256, 2)
void k_fc(const float* __restrict__ sfcw, const float* __restrict__ cfcw) {
    int img = blockIdx.y;
    const float* fcw = (img == 0) ? sfcw : cfcw;
    __shared__ float sp[9][1024];
    int tid = threadIdx.x, lane = tid & 31, wid = tid >> 5;
    int r0 = blockIdx.x * 32 + wid * 4;
    float acc[4][9];
    #pragma unroll
    for (int rr = 0; rr < 4; rr++)
        #pragma unroll
        for (int i = 0; i < 9; i++) acc[rr][i] = 0.f;

    for (int kc = 0; kc < 4096; kc += 1024) {
        __syncthreads();
        for (int idx = tid * 4; idx < 9216; idx += 1024) {
            int i = idx >> 10, kk = idx & 1023;
            *(float4*)&sp[i][kk] =
                *(const float4*)&g_pooled[(img * 9 + i) * 4096 + kc + kk];
        }
        __syncthreads();
        for (int kk = lane * 4; kk < 1024; kk += 128) {
            float4 p4[9];
            #pragma unroll
            for (int i = 0; i < 9; i++) p4[i] = *(const float4*)&sp[i][kk];
            #pragma unroll
            for (int rr = 0; rr < 4; rr++) {
                float4 w4 = *(const float4*)&fcw[(size_t)(r0 + rr) * 4096 + kc + kk];
                #pragma unroll
                for (int i = 0; i < 9; i++)
                    acc[rr][i] += w4.x * p4[i].x + w4.y * p4[i].y +
                                  w4.z * p4[i].z + w4.w * p4[i].w;
            }
        }
    }
    #pragma unroll
    for (int rr = 0; rr < 4; rr++)
        #pragma unroll
        for (int i = 0; i < 9; i++) {
            float v = acc[rr][i];
            #pragma unroll
            for (int off = 16; off; off >>= 1)
                v += __shfl_xor_sync(0xffffffffu, v, off);
            if (lane == 0) g_mats[(img * 9 + i) * 4096 + r0 + rr] += v;
        }
}

// --------------- T_i = sM_i @ cM_i (blocks 0-8) + finalize (block 9) --------
__global__ void k_T() {
    if (blockIdx.x == 9) {                     // xmean + smean finalize
        for (int t = threadIdx.x; t < 2304; t += 256) {
            if (t < 64) g_xmean[t] = g_rowsum[t] * (1.f / 65536.f);
            int i = t >> 8;
            int n = g_cnt_s256[i];
            g_smean[t] = (n > 0) ? g_ssum[t] / (float)n : 0.f;
        }
        return;
    }
    int i = blockIdx.x;
    if (!g_active[i]) return;
    __shared__ float sA[4096], sB[4096];
    for (int idx = threadIdx.x; idx < 4096; idx += 256) {
        sA[idx] = g_mats[i * 4096 + idx];          // sM
        sB[idx] = g_mats[(9 + i) * 4096 + idx];    // cM
    }
    __syncthreads();
    for (int idx = threadIdx.x; idx < 4096; idx += 256) {
        int o = idx >> 6, n = idx & 63;
        float a = 0.f;
        #pragma unroll 16
        for (int k = 0; k < 64; k++) a += sA[o * 64 + k] * sB[k * 64 + n];
        g_T[i * 4096 + idx] = a;
    }
}

// --------------- trans = (region ? T_reg @ Xc : Xc), last active region wins ---
__global__ void k_trans() {
    extern __shared__ float sT[];              // 9 * 4100 floats
    __shared__ float sxm[64];
    __shared__ int sact[9];
    int tid = threadIdx.x;
    for (int idx = tid; idx < 9 * 4096; idx += 256)
        sT[(idx >> 12) * 4100 + (idx & 4095)] = g_T[idx];
    if (tid < 64) sxm[tid] = g_xmean[tid];
    if (tid < 9) sact[tid] = g_active[tid];
    __syncthreads();
    int p = blockIdx.x * 256 + tid;
    unsigned bits = g_packed_c[p];
    int reg = -1;
    #pragma unroll
    for (int i = 8; i >= 0; i--)
        if (reg < 0 && sact[i] && ((bits >> i) & 1)) reg = i;
    float x[64];
    #pragma unroll
    for (int o = 0; o < 64; o++) x[o] = g_X[o * 65536 + p] - sxm[o];
    if (reg >= 0) {
        const float* T = &sT[reg * 4100];
        for (int o = 0; o < 64; o++) {
            const float4* t4 = reinterpret_cast<const float4*>(&T[o * 64]);
            float a0 = 0.f, a1 = 0.f, a2 = 0.f, a3 = 0.f;
            #pragma unroll
            for (int q = 0; q < 16; q++) {
                float4 tv = t4[q];
                a0 = fmaf(tv.x, x[4 * q], a0);
                a1 = fmaf(tv.y, x[4 * q + 1], a1);
                a2 = fmaf(tv.z, x[4 * q + 2], a2);
                a3 = fmaf(tv.w, x[4 * q + 3], a3);
            }
            g_trans[o * 65536 + p] = (a0 + a1) + (a2 + a3);
        }
    } else {
        #pragma unroll
        for (int o = 0; o < 64; o++) g_trans[o * 65536 + p] = x[o];
    }
    g_reg[p] = reg;
}

// ------- out = unzip_w @ trans + unzip_b + smean[region]  (f32x2 oc pairs) ---
__global__ __launch_bounds__(256, 2)
void k_unzip(const float* __restrict__ uw, const float* __restrict__ ub,
             float* __restrict__ out) {
    extern __shared__ unsigned long long dynsm[];
    unsigned long long* s_w2 = dynsm;              // [c][o2] = 64*128 u64
    unsigned long long* s_b2 = dynsm + 8192;       // [128]
    float* s_m = (float*)(dynsm + 8192 + 128);     // [9*256]
    int tid = threadIdx.x;
    for (int idx = tid; idx < 8192; idx += 256) {
        int c = idx >> 7, o2 = idx & 127;
        s_w2[idx] = pk2(uw[(2 * o2) * 64 + c], uw[(2 * o2 + 1) * 64 + c]);
    }
    if (tid < 128) s_b2[tid] = pk2(ub[2 * tid], ub[2 * tid + 1]);
    for (int idx = tid; idx < 2304; idx += 256) s_m[idx] = g_smean[idx];
    __syncthreads();
    int p = blockIdx.x * 256 + tid;
    float tr[64];
    #pragma unroll
    for (int c = 0; c < 64; c++) tr[c] = g_trans[c * 65536 + p];
    int reg = g_reg[p];
    #pragma unroll 1
    for (int t = 0; t < 8; t++) {                  // 8 tiles of 16 oc-pairs
        unsigned long long acc[16];
        #pragma unroll
        for (int q = 0; q < 16; q++) acc[q] = s_b2[t * 16 + q];
        #pragma unroll 8
        for (int c = 0; c < 64; c++) {
            unsigned long long xd = pk2(tr[c], tr[c]);
            const ulonglong2* wp =
                reinterpret_cast<const ulonglong2*>(&s_w2[c * 128 + t * 16]);
            #pragma unroll
            for (int q2 = 0; q2 < 8; q2++) {
                ulonglong2 wv = wp[q2];
                acc[2 * q2] = fma2(wv.x, xd, acc[2 * q2]);
                acc[2 * q2 + 1] = fma2(wv.y, xd, acc[2 * q2 + 1]);
            }
        }
        #pragma unroll
        for (int q = 0; q < 16; q++) {
            float lo, hi;
            upk2(acc[q], lo, hi);
            int o = (t * 16 + q) * 2;
            if (reg >= 0) { lo += s_m[reg * 256 + o]; hi += s_m[reg * 256 + o + 1]; }
            out[(size_t)o * 65536 + p] = lo;
            out[(size_t)(o + 1) * 65536 + p] = hi;
        }
    }
}

// ---------------------------------------------------------------- launch ---
extern "C" void kernel_launch(void* const* d_in, const int* in_sizes, int n_in,
                              void* d_out, int out_size) {
    (void)in_sizes; (void)n_in; (void)out_size;
    const float* cF         = (const float*)d_in[0];
    const float* sF         = (const float*)d_in[1];
    const float* content    = (const float*)d_in[2];
    const float* style      = (const float*)d_in[3];
    const int*   cmasks     = (const int*)d_in[4];
    const int*   smasks     = (const int*)d_in[5];
    const float* compress_w = (const float*)d_in[6];
    const float* compress_b = (const float*)d_in[7];
    const float* unzip_w    = (const float*)d_in[8];
    const float* unzip_b    = (const float*)d_in[9];
    const float* s_w1 = (const float*)d_in[10]; const float* s_b1 = (const float*)d_in[11];
    const float* s_w2 = (const float*)d_in[12]; const float* s_b2 = (const float*)d_in[13];
    const float* s_w3 = (const float*)d_in[14]; const float* s_b3 = (const float*)d_in[15];
    const float* s_fcw = (const float*)d_in[16]; const float* s_fcb = (const float*)d_in[17];
    const float* c_w1 = (const float*)d_in[18]; const float* c_b1 = (const float*)d_in[19];
    const float* c_w2 = (const float*)d_in[20]; const float* c_b2 = (const float*)d_in[21];
    const float* c_w3 = (const float*)d_in[22]; const float* c_b3 = (const float*)d_in[23];
    const float* c_fcw = (const float*)d_in[24]; const float* c_fcb = (const float*)d_in[25];
    float* out = (float*)d_out;

    // opt-in dynamic smem (idempotent; host API, capture-safe)
    cudaFuncSetAttribute(k_trans, cudaFuncAttributeMaxDynamicSharedMemorySize, 9 * 4100 * 4);
    cudaFuncSetAttribute(k_unzip, cudaFuncAttributeMaxDynamicSharedMemorySize,
                         8192 * 8 + 128 * 8 + 2304 * 4);

    // 1: conv1 + masks + init (independent roles fused)
    k_fat1<<<4368, 256>>>(style, content, s_w1, c_w1, s_b1, c_b1,
                          cmasks, smasks, s_fcb, c_fcb);
    // 2: mask compaction + active flags (needs masks partials)
    k_gather<<<19, 256>>>();
    // 3: (slot kept so fat2 stays the profiled 4th launch) — conv3 grid is
    //    empty-dependency-free only after fat2; use a tiny no-dep kernel? No:
    //    launch pool's dependencies later.  Here: nothing needed; fat2 next.
    // 4 <- profiled: conv2 + compress interleaved, stylesum tail (LPT order)
    k_fat2<<<1536, 256>>>(s_w2, c_w2, s_b2, c_b2, cF, compress_w, compress_b, sF);
    // 5: conv3
    k_conv3<<<dim3(8, 8, 2), 256>>>(s_w3, c_w3, s_b3, c_b3);
    // 6-8: pool, fc, T+finalize
    k_pool<<<dim3(18, 16), 256>>>();
    k_fc<<<dim3(128, 2), 256>>>(s_fcw, c_fcw);
    k_T<<<10, 256>>>();
    // 9-10: trans, unzip
    k_trans<<<256, 256, 9 * 4100 * 4>>>();
    k_unzip<<<256, 256, 8192 * 8 + 128 * 8 + 2304 * 4>>>(unzip_w, unzip_b, out);
}

// round 15
// speedup vs baseline: 1.0593x; 1.0206x over previous
#include <cuda_runtime.h>
#include <math.h>

// ------------------------------ scratch (device globals; allocation-free) ---
__device__ float g_conv1[2 * 64 * 512 * 512];   // 128 MB (style, content)
__device__ float g_conv2[2 * 32 * 256 * 256];   // 16 MB
__device__ float g_ff[2 * 16 * 128 * 128];      // conv3 outputs (style, content)
__device__ float g_X[64 * 65536];               // compressed features (uncentered)
__device__ float g_trans[64 * 65536];           // transformed features
__device__ unsigned short g_packed_c[65536];
__device__ unsigned short g_packed_s[65536];
__device__ int g_partial[256][36];              // per-block mask counts
__device__ int g_cnt_s256[9];
__device__ int g_active[9];
__device__ int g_gidx[2 * 9 * 16384];
__device__ int g_gN[2 * 9];
__device__ float g_pooled[2 * 9 * 4096];
__device__ float g_mats[2 * 9 * 4096];      // [0..8]=style sM, [9..17]=content cM
__device__ float g_T[9 * 4096];
__device__ float g_rowsum[64];
__device__ float g_xmean[64];
__device__ float g_ssum[9 * 256];
__device__ float g_smean[9 * 256];
__device__ int g_reg[65536];

// ------------------------------ packed f32x2 helpers ------------------------
__device__ __forceinline__ unsigned long long pk2(float lo, float hi) {
    unsigned long long r;
    asm("mov.b64 %0, {%1, %2};" : "=l"(r) : "f"(lo), "f"(hi));
    return r;
}
__device__ __forceinline__ unsigned long long fma2(unsigned long long a,
                                                   unsigned long long b,
                                                   unsigned long long c) {
    unsigned long long d;
    asm("fma.rn.f32x2 %0, %1, %2, %3;" : "=l"(d) : "l"(a), "l"(b), "l"(c));
    return d;
}
__device__ __forceinline__ void upk2(unsigned long long v, float& lo, float& hi) {
    asm("mov.b64 {%0, %1}, %2;" : "=f"(lo), "=f"(hi) : "l"(v));
}

// ------------------------------------------------------ conv body (shared) ---
// 3x3, stride 2, pad 1.  16 x TH output tile.  Intra-warp oc split:
//   px2 = tid&7, ocg = (tid>>3)%OCG, pyt = tid/(8*OCG)
template <int IC, int OC, int ICB, int OCT, int TH, bool RELU>
__device__ __forceinline__ void conv_body(
    char* smbase, int bx, int by,
    const float* __restrict__ in, const float* __restrict__ w,
    const float* __restrict__ bias, float* __restrict__ out,
    int inH, int inW) {
    constexpr int OCG = OC / OCT;
    constexpr int PAIRS = 8 * TH;
    constexpr int PYT = 32 / OCG;          // py-thread slots (256/(8*OCG))
    constexpr int PH = PAIRS / (8 * PYT);  // pair-rows per thread
    constexpr int ROWS = 2 * TH + 1;
    static_assert(PH >= 1, "tile too small");

    float* s_in = reinterpret_cast<float*>(smbase);                 // [ICB][ROWS][36]
    unsigned long long* s_w2 = reinterpret_cast<unsigned long long*>(
        smbase + ICB * ROWS * 36 * 4);                              // [ICB][9][OC]

    const int tid = threadIdx.x;
    const int px2 = tid & 7;
    const int ocg = (tid >> 3) % OCG;
    const int pyt = tid / (8 * OCG);
    const int px = px2 * 2;
    const int py = pyt * PH;
    const int outH = inH >> 1, outW = inW >> 1;
    const int ox0 = bx * 16, oy0 = by * TH;

    unsigned long long acc[OCT][PH];
    #pragma unroll
    for (int o = 0; o < OCT; o++) {
        float b = bias[ocg * OCT + o];
        #pragma unroll
        for (int ph = 0; ph < PH; ph++) acc[o][ph] = pk2(b, b);
    }

    for (int c0 = 0; c0 < IC; c0 += ICB) {
        __syncthreads();
        for (int idx = tid; idx < ICB * ROWS * 33; idx += 256) {
            int c = idx / (ROWS * 33), r = idx % (ROWS * 33), yy = r / 33, xx = r % 33;
            int iy = 2 * oy0 - 1 + yy, ix = 2 * ox0 - 1 + xx;
            float v = 0.f;
            if (iy >= 0 && iy < inH && ix >= 0 && ix < inW)
                v = in[((size_t)(c0 + c) * inH + iy) * inW + ix];
            s_in[(c * ROWS + yy) * 36 + xx] = v;
        }
        for (int idx = tid; idx < ICB * 9 * OC; idx += 256) {
            int c = idx / (9 * OC), r = idx % (9 * OC), k = r / OC, o = r % OC;
            float wv = w[(o * IC + c0 + c) * 9 + k];
            s_w2[idx] = pk2(wv, wv);
        }
        __syncthreads();
        #pragma unroll
        for (int c = 0; c < ICB; c++)
            #pragma unroll
            for (int ky = 0; ky < 3; ky++) {
                // hoisted row loads: 6 floats per ph via LDS.128 + LDS.64
                float4 v03[PH];
                float2 v45[PH];
                #pragma unroll
                for (int ph = 0; ph < PH; ph++) {
                    const float* rp = &s_in[(c * ROWS + 2 * (py + ph) + ky) * 36 + 2 * px];
                    v03[ph] = *reinterpret_cast<const float4*>(rp);
                    v45[ph] = *reinterpret_cast<const float2*>(rp + 4);
                }
                #pragma unroll
                for (int kx = 0; kx < 3; kx++) {
                    unsigned long long iv[PH];
                    #pragma unroll
                    for (int ph = 0; ph < PH; ph++)
                        iv[ph] = (kx == 0) ? pk2(v03[ph].x, v03[ph].z)
                               : (kx == 1) ? pk2(v03[ph].y, v03[ph].w)
                                           : pk2(v03[ph].z, v45[ph].x);
                    const ulonglong2* wp = reinterpret_cast<const ulonglong2*>(
                        &s_w2[(c * 9 + ky * 3 + kx) * OC + ocg * OCT]);
                    #pragma unroll
                    for (int q = 0; q < OCT / 2; q++) {
                        ulonglong2 wv = wp[q];
                        #pragma unroll
                        for (int ph = 0; ph < PH; ph++) {
                            acc[2 * q][ph] = fma2(wv.x, iv[ph], acc[2 * q][ph]);
                            acc[2 * q + 1][ph] = fma2(wv.y, iv[ph], acc[2 * q + 1][ph]);
                        }
                    }
                }
            }
    }
    #pragma unroll
    for (int o = 0; o < OCT; o++) {
        int oc = ocg * OCT + o;
        #pragma unroll
        for (int ph = 0; ph < PH; ph++) {
            float lo, hi;
            upk2(acc[o][ph], lo, hi);
            if (RELU) { lo = fmaxf(lo, 0.f); hi = fmaxf(hi, 0.f); }
            int oy = oy0 + py + ph, ox = ox0 + px;
            float2* op = reinterpret_cast<float2*>(&out[((size_t)oc * outH + oy) * outW + ox]);
            *op = make_float2(lo, hi);
        }
    }
}

// ------------------------------------------------- init body (16 blocks) ---
__device__ void init_body(int blk, const float* __restrict__ sfcb,
                          const float* __restrict__ cfcb) {
    int t = blk * 256 + threadIdx.x;              // 0..4095
    float sv = sfcb[t], cv = cfcb[t];
    #pragma unroll
    for (int i = 0; i < 9; i++) {
        g_mats[i * 4096 + t] = sv;
        g_mats[(9 + i) * 4096 + t] = cv;
        g_pooled[i * 4096 + t] = 0.f;
        g_pooled[(9 + i) * 4096 + t] = 0.f;
    }
    if (t < 64) g_rowsum[t] = 0.f;
    if (t < 2304) g_ssum[t] = 0.f;
}

// --------------------- masks body (256 blocks; per-block partial counts) ---
__device__ void masks_body(int blk, const int* __restrict__ cm,
                           const int* __restrict__ smk, int* s_cnt) {
    int tid = threadIdx.x;
    if (tid < 36) s_cnt[tid] = 0;
    __syncthreads();
    int p = blk * 256 + tid;
    int y = p >> 8, x = p & 255;
    int even = ((y & 1) == 0) && ((x & 1) == 0);
    unsigned pc = 0, ps = 0;
    #pragma unroll
    for (int i = 0; i < 9; i++) {
        int cb = (cm[i * 65536 + p] == 1);
        int sb = (smk[i * 65536 + p] == 1);
        if (cb) pc |= 1u << i;
        if (sb) ps |= 1u << i;
        unsigned bc = __ballot_sync(0xffffffffu, cb);
        unsigned bs = __ballot_sync(0xffffffffu, sb);
        unsigned bc1 = __ballot_sync(0xffffffffu, cb && even);
        unsigned bs1 = __ballot_sync(0xffffffffu, sb && even);
        if ((tid & 31) == 0) {
            atomicAdd(&s_cnt[i], __popc(bc));
            atomicAdd(&s_cnt[9 + i], __popc(bs));
            atomicAdd(&s_cnt[18 + i], __popc(bc1));
            atomicAdd(&s_cnt[27 + i], __popc(bs1));
        }
    }
    g_packed_c[p] = (unsigned short)pc;
    g_packed_s[p] = (unsigned short)ps;
    __syncthreads();
    if (tid < 36) g_partial[blk][tid] = s_cnt[tid];
}

// -------- compress half: X[o-half] = compress_w @ cF + b, 32 oc per block ---
__device__ void compress_half(char* smbase, int blk, const float* __restrict__ cF,
                              const float* __restrict__ cw, const float* __restrict__ cb) {
    unsigned long long* s_w = reinterpret_cast<unsigned long long*>(smbase); // [64][16]
    int tid = threadIdx.x;
    int p = (blk >> 1) * 256 + tid;
    int o2base = (blk & 1) * 16;
    unsigned long long acc[16];
    #pragma unroll
    for (int o2 = 0; o2 < 16; o2++) {
        int og = o2base + o2;
        acc[o2] = pk2(cb[2 * og], cb[2 * og + 1]);
    }
    for (int c0 = 0; c0 < 256; c0 += 64) {
        __syncthreads();
        for (int idx = tid; idx < 1024; idx += 256) {
            int c = idx >> 4, o2 = idx & 15;
            int og = o2base + o2;
            s_w[idx] = pk2(cw[(2 * og) * 256 + c0 + c],
                           cw[(2 * og + 1) * 256 + c0 + c]);
        }
        __syncthreads();
        for (int c = 0; c < 64; c++) {
            float v = cF[(c0 + c) * 65536 + p];
            unsigned long long vp = pk2(v, v);
            const ulonglong2* wq = reinterpret_cast<const ulonglong2*>(&s_w[c * 16]);
            #pragma unroll
            for (int q = 0; q < 8; q++) {
                ulonglong2 wv = wq[q];
                acc[2 * q] = fma2(wv.x, vp, acc[2 * q]);
                acc[2 * q + 1] = fma2(wv.y, vp, acc[2 * q + 1]);
            }
        }
    }
    int lane = tid & 31;
    #pragma unroll
    for (int o2 = 0; o2 < 16; o2++) {
        int og = o2base + o2;
        float lo, hi;
        upk2(acc[o2], lo, hi);
        g_X[(2 * og) * 65536 + p] = lo;
        g_X[(2 * og + 1) * 65536 + p] = hi;
        float a = lo, b = hi;
        a += __shfl_down_sync(0xffffffffu, a, 16);
        b += __shfl_down_sync(0xffffffffu, b, 16);
        a += __shfl_down_sync(0xffffffffu, a, 8);
        b += __shfl_down_sync(0xffffffffu, b, 8);
        a += __shfl_down_sync(0xffffffffu, a, 4);
        b += __shfl_down_sync(0xffffffffu, b, 4);
        a += __shfl_down_sync(0xffffffffu, a, 2);
        b += __shfl_down_sync(0xffffffffu, b, 2);
        a += __shfl_down_sync(0xffffffffu, a, 1);
        b += __shfl_down_sync(0xffffffffu, b, 1);
        if (lane == 0) {
            atomicAdd(&g_rowsum[2 * og], a);
            atomicAdd(&g_rowsum[2 * og + 1], b);
        }
    }
}

// --------------------- per-region style channel sums (512 blocks, 2/chan) ---
__device__ void stylesum_body(int blk, const float* __restrict__ sF) {
    int tid = threadIdx.x;
    int c = blk >> 1;
    int base = (blk & 1) * 32768;
    float acc[9];
    #pragma unroll
    for (int i = 0; i < 9; i++) acc[i] = 0.f;
    const float* fc = sF + c * 65536;
    for (int k = 0; k < 128; k++) {
        int p = base + k * 256 + tid;
        float v = fc[p];
        unsigned bits = g_packed_s[p];
        #pragma unroll
        for (int i = 0; i < 9; i++)
            acc[i] += ((bits >> i) & 1) ? v : 0.f;
    }
    int lane = tid & 31;
    #pragma unroll
    for (int i = 0; i < 9; i++) {
        float v = acc[i];
        v += __shfl_down_sync(0xffffffffu, v, 16);
        v += __shfl_down_sync(0xffffffffu, v, 8);
        v += __shfl_down_sync(0xffffffffu, v, 4);
        v += __shfl_down_sync(0xffffffffu, v, 2);
        v += __shfl_down_sync(0xffffffffu, v, 1);
        if (lane == 0) atomicAdd(&g_ssum[i * 256 + c], v);
    }
}

// ------ FAT 1: conv1 first (blocks 0-4095), masks (4096-4351), init last ----
__global__ __launch_bounds__(256, 3)
void k_fat1(const float* __restrict__ style, const float* __restrict__ content,
            const float* __restrict__ w1s, const float* __restrict__ w1c,
            const float* __restrict__ b1s, const float* __restrict__ b1c,
            const int* __restrict__ cm, const int* __restrict__ smk,
            const float* __restrict__ sfcb, const float* __restrict__ cfcb) {
    __shared__ __align__(16) char sm[3 * 17 * 36 * 4 + 3 * 9 * 64 * 8];  // 21168
    int b = blockIdx.x;
    if (b < 4096) {
        int bx = b & 31, by = (b >> 5) & 63, img = b >> 11;
        conv_body<3, 64, 3, 8, 8, true>(
            sm, bx, by, img ? content : style, img ? w1c : w1s,
            img ? b1c : b1s, &g_conv1[(size_t)img * 64 * 512 * 512], 1024, 1024);
    } else if (b < 4352) {
        masks_body(b - 4096, cm, smk, reinterpret_cast<int*>(sm));
    } else {
        init_body(b - 4352, sfcb, cfcb);
    }
}

// ---- FAT 2: conv2 (512) + compress (512) interleaved first, stylesum last --
__global__ __launch_bounds__(256, 3)
void k_fat2(const float* __restrict__ w2s, const float* __restrict__ w2c,
            const float* __restrict__ b2s, const float* __restrict__ b2c,
            const float* __restrict__ cF, const float* __restrict__ cw,
            const float* __restrict__ cb, const float* __restrict__ sF) {
    __shared__ __align__(16) char sm[4 * 33 * 36 * 4 + 4 * 9 * 32 * 8];  // 28224
    int b = blockIdx.x;
    if (b < 1024) {
        int idx = b >> 1;
        if ((b & 1) == 0) {
            int bx = idx & 15, by = (idx >> 4) & 15, img = idx >> 8;
            conv_body<64, 32, 4, 8, 16, true>(
                sm, bx, by, &g_conv1[(size_t)img * 64 * 512 * 512],
                img ? w2c : w2s, img ? b2c : b2s,
                &g_conv2[(size_t)img * 32 * 256 * 256], 512, 512);
        } else {
            compress_half(sm, idx, cF, cw, cb);
        }
    } else {
        stylesum_body(b - 1024, sF);
    }
}

// ------------------------- conv3: 256 small blocks (OCT=4, TH=8), 3 CTAs/SM -
__global__ __launch_bounds__(256, 3)
void k_conv3(const float* __restrict__ w3s, const float* __restrict__ w3c,
             const float* __restrict__ b3s, const float* __restrict__ b3c) {
    __shared__ __align__(16) char sm[4 * 17 * 36 * 4 + 4 * 9 * 16 * 8];  // 14400
    int img = blockIdx.z;
    conv_body<32, 16, 4, 4, 8, false>(
        sm, blockIdx.x, blockIdx.y, &g_conv2[(size_t)img * 32 * 256 * 256],
        img ? w3c : w3s, img ? b3c : b3s,
        &g_ff[(size_t)img * 16 * 128 * 128], 256, 256);
}

// ------------ mask compaction (blocks 0-17) + active/counts (block 18) ------
__global__ void k_gather() {
    int tid = threadIdx.x, lane = tid & 31, wid = tid >> 5;
    if (blockIdx.x == 18) {                    // active flags + s256 counts
        __shared__ int sums[36];
        if (tid < 36) {
            int s = 0;
            for (int b = 0; b < 256; b++) s += g_partial[b][tid];
            sums[tid] = s;
        }
        __syncthreads();
        if (tid < 9) {
            g_active[tid] = (sums[tid] >= 10) && (sums[9 + tid] >= 10) &&
                            (sums[18 + tid] >= 10) && (sums[27 + tid] >= 10);
            g_cnt_s256[tid] = sums[9 + tid];
        }
        return;
    }
    int img = blockIdx.x / 9, i = blockIdx.x % 9;
    const unsigned short* pk = (img == 0) ? g_packed_s : g_packed_c;

    __shared__ unsigned s_words[512];
    __shared__ int s_wsum[8];

    for (int widx = wid; widx < 512; widx += 8) {
        int pos = widx * 32 + lane;
        int yy = pos >> 7, xx = pos & 127;
        int p = (yy << 9) | (xx << 1);          // (2y)*256 + 2x
        unsigned b = __ballot_sync(0xffffffffu, (pk[p] >> i) & 1);
        if (lane == 0) s_words[widx] = b;
    }
    __syncthreads();

    unsigned w0 = s_words[2 * tid], w1 = s_words[2 * tid + 1];
    int c2 = __popc(w0) + __popc(w1);
    int v = c2;
    #pragma unroll
    for (int d = 1; d < 32; d <<= 1) {
        int n = __shfl_up_sync(0xffffffffu, v, d);
        if (lane >= d) v += n;
    }
    if (lane == 31) s_wsum[wid] = v;
    __syncthreads();
    if (wid == 0 && lane < 8) {
        int t = s_wsum[lane];
        #pragma unroll
        for (int d = 1; d < 8; d <<= 1) {
            int n = __shfl_up_sync(0xffu, t, d);
            if (lane >= d) t += n;
        }
        s_wsum[lane] = t;
    }
    __syncthreads();
    int base = v - c2 + (wid ? s_wsum[wid - 1] : 0);   // exclusive prefix

    int* gx = g_gidx + (img * 9 + i) * 16384;
    int o = base, pb = tid * 64;
    unsigned m = w0;
    while (m) { int b = __ffs(m) - 1; m &= m - 1; gx[o++] = pb + b; }
    m = w1; pb += 32;
    while (m) { int b = __ffs(m) - 1; m &= m - 1; gx[o++] = pb + b; }
    if (tid == 255) g_gN[img * 9 + i] = base + c2;
}

// ------------------------- adaptive max pool 256: block per (img,reg,chan) ---
__global__ void k_pool() {
    int img = blockIdx.x / 9, i = blockIdx.x % 9, c = blockIdx.y;
    int N = g_gN[img * 9 + i];
    if (N < 10) return;
    int j = threadIdx.x;                       // bin 0..255
    int s = (j * N) >> 8;
    int e = ((j + 1) * N + 255) >> 8;
    const float* fc = g_ff + img * 16 * 16384 + c * 16384;
    const int* gx = g_gidx + (img * 9 + i) * 16384;
    float m = -3.4e38f;
    for (int r = s; r < e; r++) m = fmaxf(m, fc[gx[r]]);
    g_pooled[(img * 9 + i) * 4096 + c * 256 + j] = m;
}

// ------ FC: mats[img][i][r] += fcw[r,:] @ pooled[img][i]  (coalesced k) -----
__global__ __launch_bounds__(256, 2)
void k_fc(const float* __restrict__ sfcw, const float* __restrict__ cfcw) {
    int img = blockIdx.y;
    const float* fcw = (img == 0) ? sfcw : cfcw;
    __shared__ float sp[9][1024];
    int tid = threadIdx.x, lane = tid & 31, wid = tid >> 5;
    int r0 = blockIdx.x * 32 + wid * 4;
    float acc[4][9];
    #pragma unroll
    for (int rr = 0; rr < 4; rr++)
        #pragma unroll
        for (int i = 0; i < 9; i++) acc[rr][i] = 0.f;

    for (int kc = 0; kc < 4096; kc += 1024) {
        __syncthreads();
        for (int idx = tid * 4; idx < 9216; idx += 1024) {
            int i = idx >> 10, kk = idx & 1023;
            *(float4*)&sp[i][kk] =
                *(const float4*)&g_pooled[(img * 9 + i) * 4096 + kc + kk];
        }
        __syncthreads();
        for (int kk = lane * 4; kk < 1024; kk += 128) {
            float4 p4[9];
            #pragma unroll
            for (int i = 0; i < 9; i++) p4[i] = *(const float4*)&sp[i][kk];
            #pragma unroll
            for (int rr = 0; rr < 4; rr++) {
                float4 w4 = *(const float4*)&fcw[(size_t)(r0 + rr) * 4096 + kc + kk];
                #pragma unroll
                for (int i = 0; i < 9; i++)
                    acc[rr][i] += w4.x * p4[i].x + w4.y * p4[i].y +
                                  w4.z * p4[i].z + w4.w * p4[i].w;
            }
        }
    }
    #pragma unroll
    for (int rr = 0; rr < 4; rr++)
        #pragma unroll
        for (int i = 0; i < 9; i++) {
            float v = acc[rr][i];
            #pragma unroll
            for (int off = 16; off; off >>= 1)
                v += __shfl_xor_sync(0xffffffffu, v, off);
            if (lane == 0) g_mats[(img * 9 + i) * 4096 + r0 + rr] += v;
        }
}

// --------------- T_i = sM_i @ cM_i (blocks 0-8) + finalize (block 9) --------
__global__ void k_T() {
    if (blockIdx.x == 9) {                     // xmean + smean finalize
        for (int t = threadIdx.x; t < 2304; t += 256) {
            if (t < 64) g_xmean[t] = g_rowsum[t] * (1.f / 65536.f);
            int i = t >> 8;
            int n = g_cnt_s256[i];
            g_smean[t] = (n > 0) ? g_ssum[t] / (float)n : 0.f;
        }
        return;
    }
    int i = blockIdx.x;
    if (!g_active[i]) return;
    __shared__ float sA[4096], sB[4096];
    for (int idx = threadIdx.x; idx < 4096; idx += 256) {
        sA[idx] = g_mats[i * 4096 + idx];          // sM
        sB[idx] = g_mats[(9 + i) * 4096 + idx];    // cM
    }
    __syncthreads();
    for (int idx = threadIdx.x; idx < 4096; idx += 256) {
        int o = idx >> 6, n = idx & 63;
        float a = 0.f;
        #pragma unroll 16
        for (int k = 0; k < 64; k++) a += sA[o * 64 + k] * sB[k * 64 + n];
        g_T[i * 4096 + idx] = a;
    }
}

// --------------- trans = (region ? T_reg @ Xc : Xc), last active region wins ---
__global__ void k_trans() {
    extern __shared__ float sT[];              // 9 * 4100 floats
    __shared__ float sxm[64];
    __shared__ int sact[9];
    int tid = threadIdx.x;
    for (int idx = tid; idx < 9 * 4096; idx += 256)
        sT[(idx >> 12) * 4100 + (idx & 4095)] = g_T[idx];
    if (tid < 64) sxm[tid] = g_xmean[tid];
    if (tid < 9) sact[tid] = g_active[tid];
    __syncthreads();
    int p = blockIdx.x * 256 + tid;
    unsigned bits = g_packed_c[p];
    int reg = -1;
    #pragma unroll
    for (int i = 8; i >= 0; i--)
        if (reg < 0 && sact[i] && ((bits >> i) & 1)) reg = i;
    float x[64];
    #pragma unroll
    for (int o = 0; o < 64; o++) x[o] = g_X[o * 65536 + p] - sxm[o];
    if (reg >= 0) {
        const float* T = &sT[reg * 4100];
        for (int o = 0; o < 64; o++) {
            const float4* t4 = reinterpret_cast<const float4*>(&T[o * 64]);
            float a0 = 0.f, a1 = 0.f, a2 = 0.f, a3 = 0.f;
            #pragma unroll
            for (int q = 0; q < 16; q++) {
                float4 tv = t4[q];
                a0 = fmaf(tv.x, x[4 * q], a0);
                a1 = fmaf(tv.y, x[4 * q + 1], a1);
                a2 = fmaf(tv.z, x[4 * q + 2], a2);
                a3 = fmaf(tv.w, x[4 * q + 3], a3);
            }
            g_trans[o * 65536 + p] = (a0 + a1) + (a2 + a3);
        }
    } else {
        #pragma unroll
        for (int o = 0; o < 64; o++) g_trans[o * 65536 + p] = x[o];
    }
    g_reg[p] = reg;
}

// ------- out = unzip_w @ trans + unzip_b + smean[region]  (f32x2 oc pairs) ---
__global__ __launch_bounds__(256, 2)
void k_unzip(const float* __restrict__ uw, const float* __restrict__ ub,
             float* __restrict__ out) {
    extern __shared__ unsigned long long dynsm[];
    unsigned long long* s_w2 = dynsm;              // [c][o2] = 64*128 u64
    unsigned long long* s_b2 = dynsm + 8192;       // [128]
    float* s_m = (float*)(dynsm + 8192 + 128);     // [9*256]
    int tid = threadIdx.x;
    for (int idx = tid; idx < 8192; idx += 256) {
        int c = idx >> 7, o2 = idx & 127;
        s_w2[idx] = pk2(uw[(2 * o2) * 64 + c], uw[(2 * o2 + 1) * 64 + c]);
    }
    if (tid < 128) s_b2[tid] = pk2(ub[2 * tid], ub[2 * tid + 1]);
    for (int idx = tid; idx < 2304; idx += 256) s_m[idx] = g_smean[idx];
    __syncthreads();
    int p = blockIdx.x * 256 + tid;
    float tr[64];
    #pragma unroll
    for (int c = 0; c < 64; c++) tr[c] = g_trans[c * 65536 + p];
    int reg = g_reg[p];
    #pragma unroll 1
    for (int t = 0; t < 8; t++) {                  // 8 tiles of 16 oc-pairs
        unsigned long long acc[16];
        #pragma unroll
        for (int q = 0; q < 16; q++) acc[q] = s_b2[t * 16 + q];
        #pragma unroll 8
        for (int c = 0; c < 64; c++) {
            unsigned long long xd = pk2(tr[c], tr[c]);
            const ulonglong2* wp =
                reinterpret_cast<const ulonglong2*>(&s_w2[c * 128 + t * 16]);
            #pragma unroll
            for (int q2 = 0; q2 < 8; q2++) {
                ulonglong2 wv = wp[q2];
                acc[2 * q2] = fma2(wv.x, xd, acc[2 * q2]);
                acc[2 * q2 + 1] = fma2(wv.y, xd, acc[2 * q2 + 1]);
            }
        }
        #pragma unroll
        for (int q = 0; q < 16; q++) {
            float lo, hi;
            upk2(acc[q], lo, hi);
            int o = (t * 16 + q) * 2;
            if (reg >= 0) { lo += s_m[reg * 256 + o]; hi += s_m[reg * 256 + o + 1]; }
            out[(size_t)o * 65536 + p] = lo;
            out[(size_t)(o + 1) * 65536 + p] = hi;
        }
    }
}

// ---------------------------------------------------------------- launch ---
extern "C" void kernel_launch(void* const* d_in, const int* in_sizes, int n_in,
                              void* d_out, int out_size) {
    (void)in_sizes; (void)n_in; (void)out_size;
    const float* cF         = (const float*)d_in[0];
    const float* sF         = (const float*)d_in[1];
    const float* content    = (const float*)d_in[2];
    const float* style      = (const float*)d_in[3];
    const int*   cmasks     = (const int*)d_in[4];
    const int*   smasks     = (const int*)d_in[5];
    const float* compress_w = (const float*)d_in[6];
    const float* compress_b = (const float*)d_in[7];
    const float* unzip_w    = (const float*)d_in[8];
    const float* unzip_b    = (const float*)d_in[9];
    const float* s_w1 = (const float*)d_in[10]; const float* s_b1 = (const float*)d_in[11];
    const float* s_w2 = (const float*)d_in[12]; const float* s_b2 = (const float*)d_in[13];
    const float* s_w3 = (const float*)d_in[14]; const float* s_b3 = (const float*)d_in[15];
    const float* s_fcw = (const float*)d_in[16]; const float* s_fcb = (const float*)d_in[17];
    const float* c_w1 = (const float*)d_in[18]; const float* c_b1 = (const float*)d_in[19];
    const float* c_w2 = (const float*)d_in[20]; const float* c_b2 = (const float*)d_in[21];
    const float* c_w3 = (const float*)d_in[22]; const float* c_b3 = (const float*)d_in[23];
    const float* c_fcw = (const float*)d_in[24]; const float* c_fcb = (const float*)d_in[25];
    float* out = (float*)d_out;

    // opt-in dynamic smem (idempotent; host API, capture-safe)
    cudaFuncSetAttribute(k_trans, cudaFuncAttributeMaxDynamicSharedMemorySize, 9 * 4100 * 4);
    cudaFuncSetAttribute(k_unzip, cudaFuncAttributeMaxDynamicSharedMemorySize,
                         8192 * 8 + 128 * 8 + 2304 * 4);

    // 1: conv1 + masks + init (LPT: long conv first, short roles tail)
    k_fat1<<<4368, 256>>>(style, content, s_w1, c_w1, s_b1, c_b1,
                          cmasks, smasks, s_fcb, c_fcb);
    // 2: mask compaction + active flags (needs masks partials)
    k_gather<<<19, 256>>>();
    // 3: conv2 + compress interleaved, stylesum tail (LPT order)
    k_fat2<<<1536, 256>>>(s_w2, c_w2, s_b2, c_b2, cF, compress_w, compress_b, sF);
    // 4 <- profiled: conv3, retiled for occupancy
    k_conv3<<<dim3(8, 16, 2), 256>>>(s_w3, c_w3, s_b3, c_b3);
    // 5-7: pool, fc, T+finalize
    k_pool<<<dim3(18, 16), 256>>>();
    k_fc<<<dim3(128, 2), 256>>>(s_fcw, c_fcw);
    k_T<<<10, 256>>>();
    // 8-9: trans, unzip
    k_trans<<<256, 256, 9 * 4100 * 4>>>();
    k_unzip<<<256, 256, 8192 * 8 + 128 * 8 + 2304 * 4>>>(unzip_w, unzip_b, out);
}